// round 14
// baseline (speedup 1.0000x reference)
#include <cuda_runtime.h>
#include <cuda_fp16.h>
#include <math.h>
#include <stdint.h>

#define B_  2
#define S_  2048
#define D_  1024
#define H_  16
#define HD_ 64
#define I_  4096
#define W_  256
#define TOK (B_*S_)

// ==================== scratch (__device__ globals; no allocs) ====================
__device__ float g_hid[TOK*D_];
__device__ float2 g_tab[S_*32];

__device__ __half g_xa[TOK*D_];
__device__ __half g_ca[TOK*D_];
__device__ __half g_g [(size_t)TOK*I_];
__device__ __half g_qh[TOK*D_];   // [b,h,s,d] scaled by 0.125, roped
__device__ __half g_kh[TOK*D_];   // [b,h,s,d] roped
__device__ __half g_vh[TOK*D_];   // [b,h,s,d]

// transposed weights: [N_rows, K] fp16 (w13: rows interleaved w1/w3)
__device__ __half g_wqkv[3072*1024];
__device__ __half g_wot [1024*1024];
__device__ __half g_w13 [(size_t)8192*1024];
__device__ __half g_w2t [(size_t)1024*4096];

// ==================== helpers ====================
__device__ __forceinline__ uint32_t smem_u32(const void* p) {
    return (uint32_t)__cvta_generic_to_shared(p);
}
__device__ __forceinline__ void ldsm4(uint32_t* r, uint32_t a) {
    asm volatile("ldmatrix.sync.aligned.m8n8.x4.shared.b16 {%0,%1,%2,%3}, [%4];"
                 : "=r"(r[0]), "=r"(r[1]), "=r"(r[2]), "=r"(r[3]) : "r"(a));
}
__device__ __forceinline__ void ldsm4t(uint32_t* r, uint32_t a) {
    asm volatile("ldmatrix.sync.aligned.m8n8.x4.trans.shared.b16 {%0,%1,%2,%3}, [%4];"
                 : "=r"(r[0]), "=r"(r[1]), "=r"(r[2]), "=r"(r[3]) : "r"(a));
}
__device__ __forceinline__ void mma16816h(float* d, const uint32_t* a, const uint32_t* b) {
    asm volatile("mma.sync.aligned.m16n8k16.row.col.f32.f16.f16.f32 "
                 "{%0,%1,%2,%3}, {%4,%5,%6,%7}, {%8,%9}, {%0,%1,%2,%3};"
                 : "+f"(d[0]), "+f"(d[1]), "+f"(d[2]), "+f"(d[3])
                 : "r"(a[0]), "r"(a[1]), "r"(a[2]), "r"(a[3]), "r"(b[0]), "r"(b[1]));
}
__device__ __forceinline__ void cpa16(uint32_t s, const void* g) {
    asm volatile("cp.async.cg.shared.global [%0], [%1], 16;" :: "r"(s), "l"(g) : "memory");
}
__device__ __forceinline__ uint32_t packh(float a, float b) {
    __half2 t = __floats2half2_rn(a, b);   // a in low half
    return *(uint32_t*)&t;
}

// smem tile geometry for hgemm: 128 rows x 64 halves, pitch 72 halves (144B)
#define LK2 72
#define TILE2B (128*LK2*2)      // 18432 B per tile
#define NSTG 3
#define EPI_PITCH 132           // fp32 epilogue staging pitch

// ==================== HMMA fp16 GEMM: C = A@B^T (+X) ====================
// MODE 0: C fp32   MODE 1: C = acc + X (fp32)   MODE 2: swiglu pairs -> O fp16
// MODE 4: fused rope + scatter to qh/kh/vh (QKV GEMM)
template<int MODE>
__global__ void __launch_bounds__(256, 2)
hgemm(const __half* __restrict__ A, const __half* __restrict__ B,
      float* __restrict__ C, const float* __restrict__ X,
      __half* __restrict__ O, int K, int ldc,
      const float2* __restrict__ tab,
      __half* __restrict__ qh, __half* __restrict__ kh, __half* __restrict__ vh) {
    extern __shared__ char smem[];
    uint32_t s0 = smem_u32(smem);

    int tid = threadIdx.x, lane = tid & 31, wid = tid >> 5;
    int m0 = blockIdx.y * 128, n0 = blockIdx.x * 128;
    int wm = wid & 1, wn = wid >> 1;     // 2 x 4 warps; warp tile 64(M) x 32(N)

    float acc[4][4][4];
    #pragma unroll
    for (int i = 0; i < 4; i++)
        #pragma unroll
        for (int j = 0; j < 4; j++)
            #pragma unroll
            for (int e = 0; e < 4; e++) acc[i][j][e] = 0.f;

    auto issue = [&](int slot, int kc) {
        uint32_t sa = s0 + slot * 2 * TILE2B;
        uint32_t sb = sa + TILE2B;
        #pragma unroll
        for (int t = 0; t < 4; ++t) {
            int idx = tid + t * 256;            // 1024 chunks per tile
            int r = idx >> 3, c = (idx & 7) * 8;
            cpa16(sa + (r * LK2 + c) * 2, A + (size_t)(m0 + r) * K + kc + c);
            cpa16(sb + (r * LK2 + c) * 2, B + (size_t)(n0 + r) * K + kc + c);
        }
        asm volatile("cp.async.commit_group;" ::: "memory");
    };

    int arow = wm * 64 + (lane & 15);
    int acol = (lane & 16) ? 8 : 0;
    int brow = wn * 32 + (lane & 7) + ((lane & 16) ? 8 : 0);
    int bcol = (lane & 8) ? 8 : 0;

    int NC = K >> 6;
    issue(0, 0);
    issue(1, 64);

    for (int c = 0; c < NC; ++c) {
        if (c + 1 < NC) {
            asm volatile("cp.async.wait_group 1;" ::: "memory");
        } else {
            asm volatile("cp.async.wait_group 0;" ::: "memory");
        }
        __syncthreads();      // data of stage c ready AND slot (c-1) free

        int slot = c % NSTG;
        uint32_t sA = s0 + slot * 2 * TILE2B;
        uint32_t sB = sA + TILE2B;

        #pragma unroll
        for (int ks = 0; ks < 4; ++ks) {
            uint32_t bf[2][4];
            #pragma unroll
            for (int ni2 = 0; ni2 < 2; ++ni2)
                ldsm4(bf[ni2], sB + ((brow + ni2 * 16) * LK2 + bcol + ks * 16) * 2);
            #pragma unroll
            for (int mi = 0; mi < 4; ++mi) {
                uint32_t af[4];
                ldsm4(af, sA + ((arow + mi * 16) * LK2 + acol + ks * 16) * 2);
                #pragma unroll
                for (int n8 = 0; n8 < 4; ++n8)
                    mma16816h(acc[mi][n8], af, &bf[n8 >> 1][(n8 & 1) * 2]);
            }
        }

        if (c + 2 < NC) issue((c + 2) % NSTG, (c + 2) << 6);
    }

    if (MODE == 4) {
        // ---- fused RoPE + scatter epilogue (QKV) ----
        float* st = (float*)smem;
        __syncthreads();                       // mainloop smem reads done
        #pragma unroll
        for (int mi = 0; mi < 4; ++mi)
            #pragma unroll
            for (int half = 0; half < 2; ++half) {
                int rl = wm * 64 + mi * 16 + half * 8 + (lane >> 2);
                int cl = wn * 32 + (lane & 3) * 2;
                #pragma unroll
                for (int n8 = 0; n8 < 4; ++n8) {
                    st[rl * EPI_PITCH + cl + n8 * 8]     = acc[mi][n8][half * 2 + 0];
                    st[rl * EPI_PITCH + cl + n8 * 8 + 1] = acc[mi][n8][half * 2 + 1];
                }
            }
        __syncthreads();

        int r2 = tid >> 1, side = tid & 1;     // row, which head-half of the tile
        int t = m0 + r2;
        int b = t / S_, s = t & (S_ - 1);
        int Cb = n0 + side * 64;
        int sec = Cb >> 10;                    // 0=q 1=k 2=v
        int h = (Cb & 1023) >> 6;
        const float* srow = st + r2 * EPI_PITCH + side * 64;
        __half* orow = ((sec == 0) ? qh : (sec == 1) ? kh : vh)
                       + ((size_t)(b * H_ + h) * S_ + s) * HD_;
        if (sec < 2) {
            float sc = (sec == 0) ? 0.125f : 1.0f;
            #pragma unroll
            for (int d = 0; d < 64; d += 2) {
                float x0 = srow[d],        x1 = srow[d + 1];
                float y0 = srow[d ^ 32],   y1 = srow[(d + 1) ^ 32];
                float2 c0 = tab[s * 32 + (d & 31)];
                float2 c1 = tab[s * 32 + ((d + 1) & 31)];
                float o0, o1;
                if (d < 32) { o0 = x0 * c0.x - y0 * c0.y; o1 = x1 * c1.x - y1 * c1.y; }
                else        { o0 = x0 * c0.x + y0 * c0.y; o1 = x1 * c1.x + y1 * c1.y; }
                *(uint32_t*)(orow + d) = packh(o0 * sc, o1 * sc);
            }
        } else {
            #pragma unroll
            for (int d = 0; d < 64; d += 2)
                *(uint32_t*)(orow + d) = packh(srow[d], srow[d + 1]);
        }
        return;
    }

    int rbase = m0 + wm * 64 + (lane >> 2);
    #pragma unroll
    for (int mi = 0; mi < 4; ++mi) {
        #pragma unroll
        for (int half = 0; half < 2; ++half) {
            int row = rbase + mi * 16 + half * 8;
            if (MODE == 2) {
                // swiglu: acc pairs (a,b) at cols (2p, 2p+1) -> g[row][p]
                int pldc = ldc >> 1;
                int pbase = (n0 >> 1) + wn * 16 + (lane & 3);
                #pragma unroll
                for (int n8 = 0; n8 < 4; ++n8) {
                    float a = acc[mi][n8][half * 2 + 0];
                    float b = acc[mi][n8][half * 2 + 1];
                    float g = a / (1.0f + expf(-a)) * b;
                    O[(size_t)row * pldc + pbase + n8 * 4] = __float2half(g);
                }
            } else {
                int cbase = n0 + wn * 32 + (lane & 3) * 2;
                float* crow = C + (size_t)row * ldc;
                const float* xrow = (MODE == 1) ? X + (size_t)row * ldc : nullptr;
                #pragma unroll
                for (int n8 = 0; n8 < 4; ++n8) {
                    int col = cbase + n8 * 8;
                    float2 v;
                    v.x = acc[mi][n8][half * 2 + 0];
                    v.y = acc[mi][n8][half * 2 + 1];
                    if (MODE == 1) {
                        float2 xv = *(const float2*)(xrow + col);
                        v.x += xv.x; v.y += xv.y;
                    }
                    *(float2*)(crow + col) = v;
                }
            }
        }
    }
}

// ==================== weight prep: K32 x N128 tiles + rope table ====================
// ids (blockIdx.x + base):
// [0,256)=rope table  [256,512)=wq [512,768)=wk [768,1024)=wv       (phase A)
// [1024,1280)=wo [1280,2304)=w1 [2304,3328)=w3 [3328,4352)=w2       (phase B)
__global__ void prep_all(const float* __restrict__ wq, const float* __restrict__ wk,
                         const float* __restrict__ wv, const float* __restrict__ wo,
                         const float* __restrict__ w1, const float* __restrict__ w2,
                         const float* __restrict__ w3,
                         __half* __restrict__ wqkv, __half* __restrict__ wot,
                         __half* __restrict__ w13,  __half* __restrict__ w2t,
                         float2* __restrict__ tab, int base) {
    int id = blockIdx.x + base;
    int tx = threadIdx.x, ty = threadIdx.y;     // 32 x 8
    int tid = ty * 32 + tx;

    if (id < 256) {
        // rope table: 256 blocks x 256 threads = 65536 = S*32 entries
        int i = id * 256 + tid;
        int s = i >> 5, dd = i & 31;
        double inv = exp(-(double)dd * (log(10000.0) / 32.0));
        double ang = (double)s * inv;
        tab[i] = make_float2((float)cos(ang), (float)sin(ang));
        return;
    }

    // piece select: tiles of 32(K) x 128(N)
    const float* Wp; __half* dst;
    int N, nbn, roff = 0, ldo, inter = 0, odd = 0, local;
    if (id < 512)        { Wp = wq; dst = wqkv; N = 1024; nbn = 8;  roff = 0;    ldo = 1024; local = id - 256; }
    else if (id < 768)   { Wp = wk; dst = wqkv; N = 1024; nbn = 8;  roff = 1024; ldo = 1024; local = id - 512; }
    else if (id < 1024)  { Wp = wv; dst = wqkv; N = 1024; nbn = 8;  roff = 2048; ldo = 1024; local = id - 768; }
    else if (id < 1280)  { Wp = wo; dst = wot;  N = 1024; nbn = 8;  roff = 0;    ldo = 1024; local = id - 1024; }
    else if (id < 2304)  { Wp = w1; dst = w13;  N = 4096; nbn = 32; ldo = 1024; inter = 1; odd = 0; local = id - 1280; }
    else if (id < 3328)  { Wp = w3; dst = w13;  N = 4096; nbn = 32; ldo = 1024; inter = 1; odd = 1; local = id - 2304; }
    else                 { Wp = w2; dst = w2t;  N = 1024; nbn = 8;  ldo = 4096; local = id - 3328; }

    __shared__ float t[32][129];
    int n0 = (local % nbn) * 128, k0 = (local / nbn) * 32;

    #pragma unroll
    for (int i = 0; i < 32; i += 8) {
        float4 v = *(const float4*)(Wp + (size_t)(k0 + ty + i) * N + n0 + tx * 4);
        t[ty + i][tx * 4 + 0] = v.x;
        t[ty + i][tx * 4 + 1] = v.y;
        t[ty + i][tx * 4 + 2] = v.z;
        t[ty + i][tx * 4 + 3] = v.w;
    }
    __syncthreads();

    int kk = tid & 15, nn = tid >> 4;
    #pragma unroll
    for (int ni = 0; ni < 8; ++ni) {
        int nl = nn + ni * 16;
        int n = n0 + nl;
        int row = inter ? (2 * n + odd) : (roff + n);
        uint32_t pk = packh(t[2 * kk][nl], t[2 * kk + 1][nl]);
        *(uint32_t*)(dst + (size_t)row * ldo + k0 + 2 * kk) = pk;
    }
}

// ==================== LayerNorm -> fp16 ====================
__global__ void ln_h(const float* __restrict__ x, const float* __restrict__ g,
                     const float* __restrict__ b, __half* __restrict__ y) {
    int t = blockIdx.x, tid = threadIdx.x;
    const float4* xr = (const float4*)(x + (size_t)t * D_);
    float4 xv = xr[tid];
    __shared__ float rbuf[8];
    __shared__ float s_mean, s_rstd;

    float s = xv.x + xv.y + xv.z + xv.w;
    #pragma unroll
    for (int o = 16; o; o >>= 1) s += __shfl_xor_sync(~0u, s, o);
    if ((tid & 31) == 0) rbuf[tid >> 5] = s;
    __syncthreads();
    if (tid == 0) {
        float m = 0.f;
        #pragma unroll
        for (int i = 0; i < 8; i++) m += rbuf[i];
        s_mean = m * (1.0f / D_);
    }
    __syncthreads();
    float mean = s_mean;
    float dx = xv.x - mean, dy = xv.y - mean, dz = xv.z - mean, dw = xv.w - mean;
    float s2 = dx*dx + dy*dy + dz*dz + dw*dw;
    #pragma unroll
    for (int o = 16; o; o >>= 1) s2 += __shfl_xor_sync(~0u, s2, o);
    if ((tid & 31) == 0) rbuf[tid >> 5] = s2;
    __syncthreads();
    if (tid == 0) {
        float v = 0.f;
        #pragma unroll
        for (int i = 0; i < 8; i++) v += rbuf[i];
        s_rstd = rsqrtf(v * (1.0f / D_) + 1e-6f);
    }
    __syncthreads();
    float rstd = s_rstd;
    const float4 gv = ((const float4*)g)[tid];
    const float4 bv = ((const float4*)b)[tid];
    size_t base = (size_t)t * D_ + tid * 4;
    y[base+0] = __float2half(dx * rstd * gv.x + bv.x);
    y[base+1] = __float2half(dy * rstd * gv.y + bv.y);
    y[base+2] = __float2half(dz * rstd * gv.z + bv.z);
    y[base+3] = __float2half(dw * rstd * gv.w + bv.w);
}

// ==================== flash attention (HMMA fp16, sliding window 256) ====================
#define LK_ 72
__global__ void __launch_bounds__(256, 2)
attn_mma(const __half* __restrict__ qh, const __half* __restrict__ kh,
         const __half* __restrict__ vh, __half* __restrict__ ch) {
    extern __shared__ char smem[];
    uint32_t sQ = smem_u32(smem);
    uint32_t sK = sQ + 128 * LK_ * 2;
    uint32_t sV = sK + 128 * LK_ * 2;

    int q0 = blockIdx.x * 128;
    int h = blockIdx.y, bi = blockIdx.z;
    int tid = threadIdx.x, lane = tid & 31, w = tid >> 5;
    size_t bh = ((size_t)(bi * H_ + h)) * S_;

    for (int i = tid; i < 128 * 8; i += 256) {
        int r = i >> 3, c8 = (i & 7) * 8;
        uint4 v = *(const uint4*)(qh + (bh + q0 + r) * HD_ + c8);
        *(uint4*)(smem + (r * LK_ + c8) * 2) = v;
    }
    __syncthreads();

    uint32_t qf[4][4];
    {
        int ar = w * 16 + (lane & 15);
        int ac = (lane & 16) ? 8 : 0;
        #pragma unroll
        for (int kc = 0; kc < 4; ++kc)
            ldsm4(qf[kc], sQ + (ar * LK_ + ac + kc * 16) * 2);
    }

    float O[8][4];
    #pragma unroll
    for (int i = 0; i < 8; i++) { O[i][0]=0; O[i][1]=0; O[i][2]=0; O[i][3]=0; }
    float rm0 = -1e30f, rm1 = -1e30f, l0 = 0.f, l1 = 0.f;

    int g = lane >> 2, tq = lane & 3;
    int qrow0 = q0 + w * 16 + g;

    #pragma unroll
    for (int it = 0; it < 3; ++it) {
        int ord = 2 - it;                    // diagonal tile first
        int kbase = q0 - 256 + ord * 128;
        if (kbase + 128 <= 0) continue;

        __syncthreads();
        for (int i = tid; i < 128 * 8; i += 256) {
            int r = i >> 3, c8 = (i & 7) * 8;
            int krow = kbase + r; if (krow < 0) krow = 0;
            uint4 kv = *(const uint4*)(kh + (bh + krow) * HD_ + c8);
            uint4 vv = *(const uint4*)(vh + (bh + krow) * HD_ + c8);
            *(uint4*)(smem + (128 * LK_ + r * LK_ + c8) * 2) = kv;
            *(uint4*)(smem + (256 * LK_ + r * LK_ + c8) * 2) = vv;
        }
        __syncthreads();

        float sf[16][4];
        {
            int br = (lane & 7) + ((lane & 16) ? 8 : 0);
            int bc = (lane & 8) ? 8 : 0;
            #pragma unroll
            for (int ni2 = 0; ni2 < 8; ++ni2) {
                float s4[8] = {0,0,0,0,0,0,0,0};
                #pragma unroll
                for (int kc = 0; kc < 4; ++kc) {
                    uint32_t kf[4];
                    ldsm4(kf, sK + ((ni2 * 16 + br) * LK_ + bc + kc * 16) * 2);
                    mma16816h(s4,     qf[kc], kf + 0);
                    mma16816h(s4 + 4, qf[kc], kf + 2);
                }
                #pragma unroll
                for (int e = 0; e < 4; e++) { sf[2*ni2][e] = s4[e]; sf[2*ni2+1][e] = s4[4+e]; }
            }
        }

        float tm0 = -1e30f, tm1 = -1e30f;
        #pragma unroll
        for (int ni = 0; ni < 16; ++ni) {
            int colb = kbase + ni * 8 + tq * 2;
            #pragma unroll
            for (int e = 0; e < 2; ++e) {
                int col = colb + e;
                int r0 = qrow0 - col, r1 = qrow0 + 8 - col;
                if (!(col >= 0 && r0 >= 0 && r0 < W_)) sf[ni][e]     = -1e30f;
                if (!(col >= 0 && r1 >= 0 && r1 < W_)) sf[ni][2 + e] = -1e30f;
                tm0 = fmaxf(tm0, sf[ni][e]);
                tm1 = fmaxf(tm1, sf[ni][2 + e]);
            }
        }
        tm0 = fmaxf(tm0, __shfl_xor_sync(~0u, tm0, 1));
        tm0 = fmaxf(tm0, __shfl_xor_sync(~0u, tm0, 2));
        tm1 = fmaxf(tm1, __shfl_xor_sync(~0u, tm1, 1));
        tm1 = fmaxf(tm1, __shfl_xor_sync(~0u, tm1, 2));

        float m0 = fmaxf(rm0, tm0), m1 = fmaxf(rm1, tm1);
        float a0 = __expf(rm0 - m0), a1 = __expf(rm1 - m1);
        rm0 = m0; rm1 = m1;
        #pragma unroll
        for (int nd = 0; nd < 8; ++nd) {
            O[nd][0] *= a0; O[nd][1] *= a0; O[nd][2] *= a1; O[nd][3] *= a1;
        }
        float rs0 = 0.f, rs1 = 0.f;
        #pragma unroll
        for (int ni = 0; ni < 16; ++ni) {
            float p0 = __expf(sf[ni][0] - m0);
            float p1 = __expf(sf[ni][1] - m0);
            float p2 = __expf(sf[ni][2] - m1);
            float p3 = __expf(sf[ni][3] - m1);
            sf[ni][0] = p0; sf[ni][1] = p1; sf[ni][2] = p2; sf[ni][3] = p3;
            rs0 += p0 + p1; rs1 += p2 + p3;
        }
        rs0 += __shfl_xor_sync(~0u, rs0, 1); rs0 += __shfl_xor_sync(~0u, rs0, 2);
        rs1 += __shfl_xor_sync(~0u, rs1, 1); rs1 += __shfl_xor_sync(~0u, rs1, 2);
        l0 = l0 * a0 + rs0;
        l1 = l1 * a1 + rs1;

        #pragma unroll
        for (int j = 0; j < 8; ++j) {
            uint32_t aP[4];
            aP[0] = packh(sf[2*j][0],   sf[2*j][1]);
            aP[1] = packh(sf[2*j][2],   sf[2*j][3]);
            aP[2] = packh(sf[2*j+1][0], sf[2*j+1][1]);
            aP[3] = packh(sf[2*j+1][2], sf[2*j+1][3]);
            int sel = lane >> 3;
            int vr = 16 * j + (lane & 7) + ((sel & 1) * 8);
            #pragma unroll
            for (int np = 0; np < 4; ++np) {
                uint32_t vf[4];
                ldsm4t(vf, sV + (vr * LK_ + np * 16 + ((sel >> 1) * 8)) * 2);
                mma16816h(O[2*np],     aP, vf + 0);
                mma16816h(O[2*np + 1], aP, vf + 2);
            }
        }
    }

    float i0 = 1.0f / l0, i1 = 1.0f / l1;
    size_t r0o = ((size_t)(bi * S_ + qrow0)) * D_ + h * HD_;
    size_t r1o = ((size_t)(bi * S_ + qrow0 + 8)) * D_ + h * HD_;
    #pragma unroll
    for (int nd = 0; nd < 8; ++nd) {
        int col = nd * 8 + tq * 2;
        #pragma unroll
        for (int e = 0; e < 2; ++e) {
            ch[r0o + col + e] = __float2half(O[nd][e] * i0);
            ch[r1o + col + e] = __float2half(O[nd][2 + e] * i1);
        }
    }
}

// ==================== launch ====================
extern "C" void kernel_launch(void* const* d_in, const int* in_sizes, int n_in,
                              void* d_out, int out_size) {
    const float* hidden = (const float*)d_in[0];
    const float* wq = (const float*)d_in[1];
    const float* wk = (const float*)d_in[2];
    const float* wv = (const float*)d_in[3];
    const float* wo = (const float*)d_in[4];
    const float* w1 = (const float*)d_in[5];
    const float* w2 = (const float*)d_in[6];
    const float* w3 = (const float*)d_in[7];
    const float* ln1_g = (const float*)d_in[8];
    const float* ln1_b = (const float*)d_in[9];
    const float* ln2_g = (const float*)d_in[10];
    const float* ln2_b = (const float*)d_in[11];
    float* out = (float*)d_out;

    float *hid; float2* tab;
    __half *xa, *ca, *gg, *qh, *kh, *vh, *wqkv, *wot, *w13, *w2t;
    cudaGetSymbolAddress((void**)&hid, g_hid);
    cudaGetSymbolAddress((void**)&tab, g_tab);
    cudaGetSymbolAddress((void**)&xa, g_xa);
    cudaGetSymbolAddress((void**)&ca, g_ca);
    cudaGetSymbolAddress((void**)&gg, g_g);
    cudaGetSymbolAddress((void**)&qh, g_qh);
    cudaGetSymbolAddress((void**)&kh, g_kh);
    cudaGetSymbolAddress((void**)&vh, g_vh);
    cudaGetSymbolAddress((void**)&wqkv, g_wqkv);
    cudaGetSymbolAddress((void**)&wot, g_wot);
    cudaGetSymbolAddress((void**)&w13, g_w13);
    cudaGetSymbolAddress((void**)&w2t, g_w2t);

    const int SMEM_G = 2 * NSTG * TILE2B;      // 110592 B (3 stages x A,B; MODE4 epi reuses)
    cudaFuncSetAttribute(hgemm<1>, cudaFuncAttributeMaxDynamicSharedMemorySize, SMEM_G);
    cudaFuncSetAttribute(hgemm<2>, cudaFuncAttributeMaxDynamicSharedMemorySize, SMEM_G);
    cudaFuncSetAttribute(hgemm<4>, cudaFuncAttributeMaxDynamicSharedMemorySize, SMEM_G);
    const int SMEM_ATT = 3 * 128 * LK_ * 2;   // 55296 B
    cudaFuncSetAttribute(attn_mma, cudaFuncAttributeMaxDynamicSharedMemorySize, SMEM_ATT);

    // persistent side stream + events
    static cudaStream_t s2 = nullptr;
    static cudaEvent_t eFork = nullptr, eQkvW = nullptr, eRestW = nullptr;
    if (s2 == nullptr) {
        cudaStreamCreateWithFlags(&s2, cudaStreamNonBlocking);
        cudaEventCreateWithFlags(&eFork,  cudaEventDisableTiming);
        cudaEventCreateWithFlags(&eQkvW,  cudaEventDisableTiming);
        cudaEventCreateWithFlags(&eRestW, cudaEventDisableTiming);
    }

    // fork: weight prep on side stream
    cudaEventRecord(eFork, 0);
    cudaStreamWaitEvent(s2, eFork, 0);
    // phase A: rope table + wq/wk/wv (ids 0..1023) — needed by QKV GEMM
    prep_all<<<1024, dim3(32, 8), 0, s2>>>(wq, wk, wv, wo, w1, w2, w3,
                                           wqkv, wot, w13, w2t, tab, 0);
    cudaEventRecord(eQkvW, s2);
    // phase B: wo/w13/w2 (ids 1024..4351) — overlaps with QKV GEMM
    prep_all<<<3328, dim3(32, 8), 0, s2>>>(wq, wk, wv, wo, w1, w2, w3,
                                           wqkv, wot, w13, w2t, tab, 1024);
    cudaEventRecord(eRestW, s2);

    // --- attention sub-block (main stream) ---
    ln_h<<<TOK, 256>>>(hidden, ln1_g, ln1_b, xa);
    cudaStreamWaitEvent(0, eQkvW, 0);
    // QKV GEMM with fused rope+scatter epilogue
    hgemm<4><<<dim3(24, 32), 256, SMEM_G>>>(xa, wqkv, nullptr, nullptr, nullptr, 1024, 0,
                                            tab, qh, kh, vh);
    attn_mma<<<dim3(S_ / 128, H_, B_), 256, SMEM_ATT>>>(qh, kh, vh, ca);
    cudaStreamWaitEvent(0, eRestW, 0);     // remaining weights ready
    hgemm<1><<<dim3(8, 32), 256, SMEM_G>>>(ca, wot, hid, hidden, nullptr, 1024, D_,
                                           nullptr, nullptr, nullptr, nullptr);

    // --- SwiGLU MLP sub-block ---
    ln_h<<<TOK, 256>>>(hid, ln2_g, ln2_b, xa);
    hgemm<2><<<dim3(64, 32), 256, SMEM_G>>>(xa, w13, nullptr, nullptr, gg, 1024, 8192,
                                            nullptr, nullptr, nullptr, nullptr);
    hgemm<1><<<dim3(8, 32), 256, SMEM_G>>>(gg, w2t, out, hid, nullptr, 4096, D_,
                                           nullptr, nullptr, nullptr, nullptr);
}

// round 15
// speedup vs baseline: 1.0627x; 1.0627x over previous
#include <cuda_runtime.h>
#include <cuda_fp16.h>
#include <math.h>
#include <stdint.h>

#define B_  2
#define S_  2048
#define D_  1024
#define H_  16
#define HD_ 64
#define I_  4096
#define W_  256
#define TOK (B_*S_)
#define QKV_LD 3072

// ==================== scratch (__device__ globals; no allocs) ====================
__device__ float g_hid[TOK*D_];
__device__ float2 g_tab[S_*32];

__device__ __half g_qkvh[(size_t)TOK*QKV_LD];
__device__ __half g_xa[TOK*D_];
__device__ __half g_ca[TOK*D_];
__device__ __half g_g [(size_t)TOK*I_];
__device__ __half g_qh[TOK*D_];   // [b,h,s,d] scaled by 0.125, roped
__device__ __half g_kh[TOK*D_];   // [b,h,s,d] roped
__device__ __half g_vh[TOK*D_];   // [b,h,s,d]

// transposed weights: [N_rows, K] fp16 (w13: rows interleaved w1/w3)
__device__ __half g_wqkv[3072*1024];
__device__ __half g_wot [1024*1024];
__device__ __half g_w13 [(size_t)8192*1024];
__device__ __half g_w2t [(size_t)1024*4096];

// ==================== helpers ====================
__device__ __forceinline__ uint32_t smem_u32(const void* p) {
    return (uint32_t)__cvta_generic_to_shared(p);
}
__device__ __forceinline__ void ldsm4(uint32_t* r, uint32_t a) {
    asm volatile("ldmatrix.sync.aligned.m8n8.x4.shared.b16 {%0,%1,%2,%3}, [%4];"
                 : "=r"(r[0]), "=r"(r[1]), "=r"(r[2]), "=r"(r[3]) : "r"(a));
}
__device__ __forceinline__ void ldsm4t(uint32_t* r, uint32_t a) {
    asm volatile("ldmatrix.sync.aligned.m8n8.x4.trans.shared.b16 {%0,%1,%2,%3}, [%4];"
                 : "=r"(r[0]), "=r"(r[1]), "=r"(r[2]), "=r"(r[3]) : "r"(a));
}
__device__ __forceinline__ void mma16816h(float* d, const uint32_t* a, const uint32_t* b) {
    asm volatile("mma.sync.aligned.m16n8k16.row.col.f32.f16.f16.f32 "
                 "{%0,%1,%2,%3}, {%4,%5,%6,%7}, {%8,%9}, {%0,%1,%2,%3};"
                 : "+f"(d[0]), "+f"(d[1]), "+f"(d[2]), "+f"(d[3])
                 : "r"(a[0]), "r"(a[1]), "r"(a[2]), "r"(a[3]), "r"(b[0]), "r"(b[1]));
}
__device__ __forceinline__ void cpa16(uint32_t s, const void* g) {
    asm volatile("cp.async.cg.shared.global [%0], [%1], 16;" :: "r"(s), "l"(g) : "memory");
}
__device__ __forceinline__ uint32_t packh(float a, float b) {
    __half2 t = __floats2half2_rn(a, b);   // a in low half
    return *(uint32_t*)&t;
}

// smem tile geometry for hgemm: 128 rows x 64 halves, pitch 72 halves (144B)
#define LK2 72
#define TILE2B (128*LK2*2)      // 18432 B per tile
#define NSTG 3

// ==================== HMMA fp16 GEMM: C = A@B^T (+X) ====================
// MODE 0: C fp32   MODE 1: C = acc + X (fp32)   MODE 2: swiglu pairs -> O fp16
// MODE 3: O fp16 raw
template<int MODE>
__global__ void __launch_bounds__(256, 2)
hgemm(const __half* __restrict__ A, const __half* __restrict__ B,
      float* __restrict__ C, const float* __restrict__ X,
      __half* __restrict__ O, int K, int ldc) {
    extern __shared__ char smem[];
    uint32_t s0 = smem_u32(smem);

    int tid = threadIdx.x, lane = tid & 31, wid = tid >> 5;
    int m0 = blockIdx.y * 128, n0 = blockIdx.x * 128;
    int wm = wid & 1, wn = wid >> 1;     // 2 x 4 warps; warp tile 64(M) x 32(N)

    float acc[4][4][4];
    #pragma unroll
    for (int i = 0; i < 4; i++)
        #pragma unroll
        for (int j = 0; j < 4; j++)
            #pragma unroll
            for (int e = 0; e < 4; e++) acc[i][j][e] = 0.f;

    auto issue = [&](int slot, int kc) {
        uint32_t sa = s0 + slot * 2 * TILE2B;
        uint32_t sb = sa + TILE2B;
        #pragma unroll
        for (int t = 0; t < 4; ++t) {
            int idx = tid + t * 256;            // 1024 chunks per tile
            int r = idx >> 3, c = (idx & 7) * 8;
            cpa16(sa + (r * LK2 + c) * 2, A + (size_t)(m0 + r) * K + kc + c);
            cpa16(sb + (r * LK2 + c) * 2, B + (size_t)(n0 + r) * K + kc + c);
        }
        asm volatile("cp.async.commit_group;" ::: "memory");
    };

    int arow = wm * 64 + (lane & 15);
    int acol = (lane & 16) ? 8 : 0;
    int brow = wn * 32 + (lane & 7) + ((lane & 16) ? 8 : 0);
    int bcol = (lane & 8) ? 8 : 0;

    int NC = K >> 6;
    issue(0, 0);
    issue(1, 64);

    for (int c = 0; c < NC; ++c) {
        if (c + 1 < NC) {
            asm volatile("cp.async.wait_group 1;" ::: "memory");
        } else {
            asm volatile("cp.async.wait_group 0;" ::: "memory");
        }
        __syncthreads();      // data of stage c ready AND slot (c-1) free

        int slot = c % NSTG;
        uint32_t sA = s0 + slot * 2 * TILE2B;
        uint32_t sB = sA + TILE2B;

        #pragma unroll
        for (int ks = 0; ks < 4; ++ks) {
            uint32_t bf[2][4];
            #pragma unroll
            for (int ni2 = 0; ni2 < 2; ++ni2)
                ldsm4(bf[ni2], sB + ((brow + ni2 * 16) * LK2 + bcol + ks * 16) * 2);
            #pragma unroll
            for (int mi = 0; mi < 4; ++mi) {
                uint32_t af[4];
                ldsm4(af, sA + ((arow + mi * 16) * LK2 + acol + ks * 16) * 2);
                #pragma unroll
                for (int n8 = 0; n8 < 4; ++n8)
                    mma16816h(acc[mi][n8], af, &bf[n8 >> 1][(n8 & 1) * 2]);
            }
        }

        if (c + 2 < NC) issue((c + 2) % NSTG, (c + 2) << 6);
    }

    int rbase = m0 + wm * 64 + (lane >> 2);
    #pragma unroll
    for (int mi = 0; mi < 4; ++mi) {
        #pragma unroll
        for (int half = 0; half < 2; ++half) {
            int row = rbase + mi * 16 + half * 8;
            if (MODE == 2) {
                // swiglu: acc pairs (a,b) at cols (2p, 2p+1) -> g[row][p]
                int pldc = ldc >> 1;
                int pbase = (n0 >> 1) + wn * 16 + (lane & 3);
                #pragma unroll
                for (int n8 = 0; n8 < 4; ++n8) {
                    float a = acc[mi][n8][half * 2 + 0];
                    float b = acc[mi][n8][half * 2 + 1];
                    float g = a / (1.0f + expf(-a)) * b;
                    O[(size_t)row * pldc + pbase + n8 * 4] = __float2half(g);
                }
            } else if (MODE == 3) {
                int cbase = n0 + wn * 32 + (lane & 3) * 2;
                __half* orow = O + (size_t)row * ldc;
                #pragma unroll
                for (int n8 = 0; n8 < 4; ++n8) {
                    int col = cbase + n8 * 8;
                    *(uint32_t*)(orow + col) =
                        packh(acc[mi][n8][half * 2 + 0], acc[mi][n8][half * 2 + 1]);
                }
            } else {
                int cbase = n0 + wn * 32 + (lane & 3) * 2;
                float* crow = C + (size_t)row * ldc;
                const float* xrow = (MODE == 1) ? X + (size_t)row * ldc : nullptr;
                #pragma unroll
                for (int n8 = 0; n8 < 4; ++n8) {
                    int col = cbase + n8 * 8;
                    float2 v;
                    v.x = acc[mi][n8][half * 2 + 0];
                    v.y = acc[mi][n8][half * 2 + 1];
                    if (MODE == 1) {
                        float2 xv = *(const float2*)(xrow + col);
                        v.x += xv.x; v.y += xv.y;
                    }
                    *(float2*)(crow + col) = v;
                }
            }
        }
    }
}

// ==================== weight prep: K32 x N128 tiles + rope table ====================
// ids (blockIdx.x + base):
// phase A [0,1024): [0,256)=rope table [256,512)=wq [512,768)=wk [768,1024)=wv
// phase B [1024,4352): [1024,1280)=wo [1280,2304)=w1 [2304,3328)=w3 [3328,4352)=w2
__global__ void prep_all(const float* __restrict__ wq, const float* __restrict__ wk,
                         const float* __restrict__ wv, const float* __restrict__ wo,
                         const float* __restrict__ w1, const float* __restrict__ w2,
                         const float* __restrict__ w3,
                         __half* __restrict__ wqkv, __half* __restrict__ wot,
                         __half* __restrict__ w13,  __half* __restrict__ w2t,
                         float2* __restrict__ tab, int base) {
    int id = blockIdx.x + base;
    int tx = threadIdx.x, ty = threadIdx.y;     // 32 x 8
    int tid = ty * 32 + tx;

    if (id < 256) {
        // rope table: 256 blocks x 256 threads = 65536 = S*32 entries
        int i = id * 256 + tid;
        int s = i >> 5, dd = i & 31;
        double inv = exp(-(double)dd * (log(10000.0) / 32.0));
        double ang = (double)s * inv;
        tab[i] = make_float2((float)cos(ang), (float)sin(ang));
        return;
    }

    // piece select: tiles of 32(K) x 128(N)
    const float* Wp; __half* dst;
    int N, nbn, roff = 0, ldo, inter = 0, odd = 0, local;
    if (id < 512)        { Wp = wq; dst = wqkv; N = 1024; nbn = 8;  roff = 0;    ldo = 1024; local = id - 256; }
    else if (id < 768)   { Wp = wk; dst = wqkv; N = 1024; nbn = 8;  roff = 1024; ldo = 1024; local = id - 512; }
    else if (id < 1024)  { Wp = wv; dst = wqkv; N = 1024; nbn = 8;  roff = 2048; ldo = 1024; local = id - 768; }
    else if (id < 1280)  { Wp = wo; dst = wot;  N = 1024; nbn = 8;  roff = 0;    ldo = 1024; local = id - 1024; }
    else if (id < 2304)  { Wp = w1; dst = w13;  N = 4096; nbn = 32; ldo = 1024; inter = 1; odd = 0; local = id - 1280; }
    else if (id < 3328)  { Wp = w3; dst = w13;  N = 4096; nbn = 32; ldo = 1024; inter = 1; odd = 1; local = id - 2304; }
    else                 { Wp = w2; dst = w2t;  N = 1024; nbn = 8;  ldo = 4096; local = id - 3328; }

    __shared__ float t[32][129];
    int n0 = (local % nbn) * 128, k0 = (local / nbn) * 32;

    #pragma unroll
    for (int i = 0; i < 32; i += 8) {
        float4 v = *(const float4*)(Wp + (size_t)(k0 + ty + i) * N + n0 + tx * 4);
        t[ty + i][tx * 4 + 0] = v.x;
        t[ty + i][tx * 4 + 1] = v.y;
        t[ty + i][tx * 4 + 2] = v.z;
        t[ty + i][tx * 4 + 3] = v.w;
    }
    __syncthreads();

    int kk = tid & 15, nn = tid >> 4;
    #pragma unroll
    for (int ni = 0; ni < 8; ++ni) {
        int nl = nn + ni * 16;
        int n = n0 + nl;
        int row = inter ? (2 * n + odd) : (roff + n);
        uint32_t pk = packh(t[2 * kk][nl], t[2 * kk + 1][nl]);
        *(uint32_t*)(dst + (size_t)row * ldo + k0 + 2 * kk) = pk;
    }
}

// ==================== LayerNorm -> fp16 ====================
__global__ void ln_h(const float* __restrict__ x, const float* __restrict__ g,
                     const float* __restrict__ b, __half* __restrict__ y) {
    int t = blockIdx.x, tid = threadIdx.x;
    const float4* xr = (const float4*)(x + (size_t)t * D_);
    float4 xv = xr[tid];
    __shared__ float rbuf[8];
    __shared__ float s_mean, s_rstd;

    float s = xv.x + xv.y + xv.z + xv.w;
    #pragma unroll
    for (int o = 16; o; o >>= 1) s += __shfl_xor_sync(~0u, s, o);
    if ((tid & 31) == 0) rbuf[tid >> 5] = s;
    __syncthreads();
    if (tid == 0) {
        float m = 0.f;
        #pragma unroll
        for (int i = 0; i < 8; i++) m += rbuf[i];
        s_mean = m * (1.0f / D_);
    }
    __syncthreads();
    float mean = s_mean;
    float dx = xv.x - mean, dy = xv.y - mean, dz = xv.z - mean, dw = xv.w - mean;
    float s2 = dx*dx + dy*dy + dz*dz + dw*dw;
    #pragma unroll
    for (int o = 16; o; o >>= 1) s2 += __shfl_xor_sync(~0u, s2, o);
    if ((tid & 31) == 0) rbuf[tid >> 5] = s2;
    __syncthreads();
    if (tid == 0) {
        float v = 0.f;
        #pragma unroll
        for (int i = 0; i < 8; i++) v += rbuf[i];
        s_rstd = rsqrtf(v * (1.0f / D_) + 1e-6f);
    }
    __syncthreads();
    float rstd = s_rstd;
    const float4 gv = ((const float4*)g)[tid];
    const float4 bv = ((const float4*)b)[tid];
    size_t base = (size_t)t * D_ + tid * 4;
    y[base+0] = __float2half(dx * rstd * gv.x + bv.x);
    y[base+1] = __float2half(dy * rstd * gv.y + bv.y);
    y[base+2] = __float2half(dz * rstd * gv.z + bv.z);
    y[base+3] = __float2half(dw * rstd * gv.w + bv.w);
}

// ==================== RoPE + scatter: qkvh fp16 -> q/k/v fp16 [b,h,s,d] ====================
__global__ void rope_cvt(const __half* __restrict__ qkv, const float2* __restrict__ tab,
                         __half* __restrict__ qh, __half* __restrict__ kh,
                         __half* __restrict__ vh) {
    int t = blockIdx.x;                 // token
    int tid = threadIdx.x;              // 128
    int b = t / S_, s = t & (S_ - 1);
    int d = tid & 63;
    float2 cs = tab[s * 32 + (d & 31)];
    float c = cs.x, sn = cs.y;
    const __half* row = qkv + (size_t)t * QKV_LD;

    #pragma unroll
    for (int hh = 0; hh < 8; ++hh) {
        int h = hh * 2 + (tid >> 6);
        size_t oidx = ((size_t)(b * H_ + h) * S_ + s) * HD_ + d;
        {
            float x1 = __half2float(row[h * 64 + d]);
            float x2 = __half2float(row[h * 64 + (d ^ 32)]);
            float o = (d < 32) ? (x1 * c - x2 * sn) : (x1 * c + x2 * sn);
            qh[oidx] = __float2half(o * 0.125f);
        }
        {
            float x1 = __half2float(row[1024 + h * 64 + d]);
            float x2 = __half2float(row[1024 + h * 64 + (d ^ 32)]);
            float o = (d < 32) ? (x1 * c - x2 * sn) : (x1 * c + x2 * sn);
            kh[oidx] = __float2half(o);
        }
        vh[oidx] = row[2048 + h * 64 + d];
    }
}

// ==================== flash attention (HMMA fp16, sliding window 256) ====================
#define LK_ 72
__global__ void __launch_bounds__(256, 2)
attn_mma(const __half* __restrict__ qh, const __half* __restrict__ kh,
         const __half* __restrict__ vh, __half* __restrict__ ch) {
    extern __shared__ char smem[];
    uint32_t sQ = smem_u32(smem);
    uint32_t sK = sQ + 128 * LK_ * 2;
    uint32_t sV = sK + 128 * LK_ * 2;

    int q0 = blockIdx.x * 128;
    int h = blockIdx.y, bi = blockIdx.z;
    int tid = threadIdx.x, lane = tid & 31, w = tid >> 5;
    size_t bh = ((size_t)(bi * H_ + h)) * S_;

    for (int i = tid; i < 128 * 8; i += 256) {
        int r = i >> 3, c8 = (i & 7) * 8;
        uint4 v = *(const uint4*)(qh + (bh + q0 + r) * HD_ + c8);
        *(uint4*)(smem + (r * LK_ + c8) * 2) = v;
    }
    __syncthreads();

    uint32_t qf[4][4];
    {
        int ar = w * 16 + (lane & 15);
        int ac = (lane & 16) ? 8 : 0;
        #pragma unroll
        for (int kc = 0; kc < 4; ++kc)
            ldsm4(qf[kc], sQ + (ar * LK_ + ac + kc * 16) * 2);
    }

    float O[8][4];
    #pragma unroll
    for (int i = 0; i < 8; i++) { O[i][0]=0; O[i][1]=0; O[i][2]=0; O[i][3]=0; }
    float rm0 = -1e30f, rm1 = -1e30f, l0 = 0.f, l1 = 0.f;

    int g = lane >> 2, tq = lane & 3;
    int qrow0 = q0 + w * 16 + g;

    #pragma unroll
    for (int it = 0; it < 3; ++it) {
        int ord = 2 - it;                    // diagonal tile first
        int kbase = q0 - 256 + ord * 128;
        if (kbase + 128 <= 0) continue;

        __syncthreads();
        for (int i = tid; i < 128 * 8; i += 256) {
            int r = i >> 3, c8 = (i & 7) * 8;
            int krow = kbase + r; if (krow < 0) krow = 0;
            uint4 kv = *(const uint4*)(kh + (bh + krow) * HD_ + c8);
            uint4 vv = *(const uint4*)(vh + (bh + krow) * HD_ + c8);
            *(uint4*)(smem + (128 * LK_ + r * LK_ + c8) * 2) = kv;
            *(uint4*)(smem + (256 * LK_ + r * LK_ + c8) * 2) = vv;
        }
        __syncthreads();

        float sf[16][4];
        {
            int br = (lane & 7) + ((lane & 16) ? 8 : 0);
            int bc = (lane & 8) ? 8 : 0;
            #pragma unroll
            for (int ni2 = 0; ni2 < 8; ++ni2) {
                float s4[8] = {0,0,0,0,0,0,0,0};
                #pragma unroll
                for (int kc = 0; kc < 4; ++kc) {
                    uint32_t kf[4];
                    ldsm4(kf, sK + ((ni2 * 16 + br) * LK_ + bc + kc * 16) * 2);
                    mma16816h(s4,     qf[kc], kf + 0);
                    mma16816h(s4 + 4, qf[kc], kf + 2);
                }
                #pragma unroll
                for (int e = 0; e < 4; e++) { sf[2*ni2][e] = s4[e]; sf[2*ni2+1][e] = s4[4+e]; }
            }
        }

        float tm0 = -1e30f, tm1 = -1e30f;
        #pragma unroll
        for (int ni = 0; ni < 16; ++ni) {
            int colb = kbase + ni * 8 + tq * 2;
            #pragma unroll
            for (int e = 0; e < 2; ++e) {
                int col = colb + e;
                int r0 = qrow0 - col, r1 = qrow0 + 8 - col;
                if (!(col >= 0 && r0 >= 0 && r0 < W_)) sf[ni][e]     = -1e30f;
                if (!(col >= 0 && r1 >= 0 && r1 < W_)) sf[ni][2 + e] = -1e30f;
                tm0 = fmaxf(tm0, sf[ni][e]);
                tm1 = fmaxf(tm1, sf[ni][2 + e]);
            }
        }
        tm0 = fmaxf(tm0, __shfl_xor_sync(~0u, tm0, 1));
        tm0 = fmaxf(tm0, __shfl_xor_sync(~0u, tm0, 2));
        tm1 = fmaxf(tm1, __shfl_xor_sync(~0u, tm1, 1));
        tm1 = fmaxf(tm1, __shfl_xor_sync(~0u, tm1, 2));

        float m0 = fmaxf(rm0, tm0), m1 = fmaxf(rm1, tm1);
        float a0 = __expf(rm0 - m0), a1 = __expf(rm1 - m1);
        rm0 = m0; rm1 = m1;
        #pragma unroll
        for (int nd = 0; nd < 8; ++nd) {
            O[nd][0] *= a0; O[nd][1] *= a0; O[nd][2] *= a1; O[nd][3] *= a1;
        }
        float rs0 = 0.f, rs1 = 0.f;
        #pragma unroll
        for (int ni = 0; ni < 16; ++ni) {
            float p0 = __expf(sf[ni][0] - m0);
            float p1 = __expf(sf[ni][1] - m0);
            float p2 = __expf(sf[ni][2] - m1);
            float p3 = __expf(sf[ni][3] - m1);
            sf[ni][0] = p0; sf[ni][1] = p1; sf[ni][2] = p2; sf[ni][3] = p3;
            rs0 += p0 + p1; rs1 += p2 + p3;
        }
        rs0 += __shfl_xor_sync(~0u, rs0, 1); rs0 += __shfl_xor_sync(~0u, rs0, 2);
        rs1 += __shfl_xor_sync(~0u, rs1, 1); rs1 += __shfl_xor_sync(~0u, rs1, 2);
        l0 = l0 * a0 + rs0;
        l1 = l1 * a1 + rs1;

        #pragma unroll
        for (int j = 0; j < 8; ++j) {
            uint32_t aP[4];
            aP[0] = packh(sf[2*j][0],   sf[2*j][1]);
            aP[1] = packh(sf[2*j][2],   sf[2*j][3]);
            aP[2] = packh(sf[2*j+1][0], sf[2*j+1][1]);
            aP[3] = packh(sf[2*j+1][2], sf[2*j+1][3]);
            int sel = lane >> 3;
            int vr = 16 * j + (lane & 7) + ((sel & 1) * 8);
            #pragma unroll
            for (int np = 0; np < 4; ++np) {
                uint32_t vf[4];
                ldsm4t(vf, sV + (vr * LK_ + np * 16 + ((sel >> 1) * 8)) * 2);
                mma16816h(O[2*np],     aP, vf + 0);
                mma16816h(O[2*np + 1], aP, vf + 2);
            }
        }
    }

    float i0 = 1.0f / l0, i1 = 1.0f / l1;
    size_t r0o = ((size_t)(bi * S_ + qrow0)) * D_ + h * HD_;
    size_t r1o = ((size_t)(bi * S_ + qrow0 + 8)) * D_ + h * HD_;
    #pragma unroll
    for (int nd = 0; nd < 8; ++nd) {
        int col = nd * 8 + tq * 2;
        #pragma unroll
        for (int e = 0; e < 2; ++e) {
            ch[r0o + col + e] = __float2half(O[nd][e] * i0);
            ch[r1o + col + e] = __float2half(O[nd][2 + e] * i1);
        }
    }
}

// ==================== launch ====================
extern "C" void kernel_launch(void* const* d_in, const int* in_sizes, int n_in,
                              void* d_out, int out_size) {
    const float* hidden = (const float*)d_in[0];
    const float* wq = (const float*)d_in[1];
    const float* wk = (const float*)d_in[2];
    const float* wv = (const float*)d_in[3];
    const float* wo = (const float*)d_in[4];
    const float* w1 = (const float*)d_in[5];
    const float* w2 = (const float*)d_in[6];
    const float* w3 = (const float*)d_in[7];
    const float* ln1_g = (const float*)d_in[8];
    const float* ln1_b = (const float*)d_in[9];
    const float* ln2_g = (const float*)d_in[10];
    const float* ln2_b = (const float*)d_in[11];
    float* out = (float*)d_out;

    float *hid; float2* tab;
    __half *qkvh, *xa, *ca, *gg, *qh, *kh, *vh, *wqkv, *wot, *w13, *w2t;
    cudaGetSymbolAddress((void**)&hid, g_hid);
    cudaGetSymbolAddress((void**)&tab, g_tab);
    cudaGetSymbolAddress((void**)&qkvh, g_qkvh);
    cudaGetSymbolAddress((void**)&xa, g_xa);
    cudaGetSymbolAddress((void**)&ca, g_ca);
    cudaGetSymbolAddress((void**)&gg, g_g);
    cudaGetSymbolAddress((void**)&qh, g_qh);
    cudaGetSymbolAddress((void**)&kh, g_kh);
    cudaGetSymbolAddress((void**)&vh, g_vh);
    cudaGetSymbolAddress((void**)&wqkv, g_wqkv);
    cudaGetSymbolAddress((void**)&wot, g_wot);
    cudaGetSymbolAddress((void**)&w13, g_w13);
    cudaGetSymbolAddress((void**)&w2t, g_w2t);

    const int SMEM_G = 2 * NSTG * TILE2B;      // 110592 B (3 stages x A,B)
    cudaFuncSetAttribute(hgemm<1>, cudaFuncAttributeMaxDynamicSharedMemorySize, SMEM_G);
    cudaFuncSetAttribute(hgemm<2>, cudaFuncAttributeMaxDynamicSharedMemorySize, SMEM_G);
    cudaFuncSetAttribute(hgemm<3>, cudaFuncAttributeMaxDynamicSharedMemorySize, SMEM_G);
    const int SMEM_ATT = 3 * 128 * LK_ * 2;   // 55296 B
    cudaFuncSetAttribute(attn_mma, cudaFuncAttributeMaxDynamicSharedMemorySize, SMEM_ATT);

    // persistent side stream + events
    static cudaStream_t s2 = nullptr;
    static cudaEvent_t eFork = nullptr, eQkvW = nullptr, eRestW = nullptr;
    if (s2 == nullptr) {
        cudaStreamCreateWithFlags(&s2, cudaStreamNonBlocking);
        cudaEventCreateWithFlags(&eFork,  cudaEventDisableTiming);
        cudaEventCreateWithFlags(&eQkvW,  cudaEventDisableTiming);
        cudaEventCreateWithFlags(&eRestW, cudaEventDisableTiming);
    }

    // fork: weight prep on side stream
    cudaEventRecord(eFork, 0);
    cudaStreamWaitEvent(s2, eFork, 0);
    // phase A: rope table + wq/wk/wv (ids 0..1023) — covers QKV GEMM + rope_cvt
    prep_all<<<1024, dim3(32, 8), 0, s2>>>(wq, wk, wv, wo, w1, w2, w3,
                                           wqkv, wot, w13, w2t, tab, 0);
    cudaEventRecord(eQkvW, s2);
    // phase B: wo/w13/w2 (ids 1024..4351) — overlaps QKV GEMM + attention
    prep_all<<<3328, dim3(32, 8), 0, s2>>>(wq, wk, wv, wo, w1, w2, w3,
                                           wqkv, wot, w13, w2t, tab, 1024);
    cudaEventRecord(eRestW, s2);

    // --- attention sub-block (main stream) ---
    ln_h<<<TOK, 256>>>(hidden, ln1_g, ln1_b, xa);
    cudaStreamWaitEvent(0, eQkvW, 0);
    hgemm<3><<<dim3(24, 32), 256, SMEM_G>>>(xa, wqkv, nullptr, nullptr, qkvh, 1024, QKV_LD);
    rope_cvt<<<TOK, 128>>>(qkvh, tab, qh, kh, vh);
    attn_mma<<<dim3(S_ / 128, H_, B_), 256, SMEM_ATT>>>(qh, kh, vh, ca);
    cudaStreamWaitEvent(0, eRestW, 0);     // wo/w13/w2 ready (hidden under QKV+attn)
    hgemm<1><<<dim3(8, 32), 256, SMEM_G>>>(ca, wot, hid, hidden, nullptr, 1024, D_);

    // --- SwiGLU MLP sub-block ---
    ln_h<<<TOK, 256>>>(hid, ln2_g, ln2_b, xa);
    hgemm<2><<<dim3(64, 32), 256, SMEM_G>>>(xa, w13, nullptr, nullptr, gg, 1024, 8192);
    hgemm<1><<<dim3(8, 32), 256, SMEM_G>>>(gg, w2t, out, hid, nullptr, 4096, D_);
}

// round 16
// speedup vs baseline: 1.0787x; 1.0151x over previous
#include <cuda_runtime.h>
#include <cuda_fp16.h>
#include <math.h>
#include <stdint.h>

#define B_  2
#define S_  2048
#define D_  1024
#define H_  16
#define HD_ 64
#define I_  4096
#define W_  256
#define TOK (B_*S_)
#define QKV_LD 3072

// ==================== scratch (__device__ globals; no allocs) ====================
__device__ float g_hid[TOK*D_];
__device__ float2 g_tab[S_*32];

__device__ __half g_qkvh[(size_t)TOK*QKV_LD];
__device__ __half g_xa[TOK*D_];
__device__ __half g_ca[TOK*D_];
__device__ __half g_g [(size_t)TOK*I_];
__device__ __half g_qh[TOK*D_];   // [b,h,s,d] scaled by 0.125, roped
__device__ __half g_kh[TOK*D_];   // [b,h,s,d] roped
__device__ __half g_vh[TOK*D_];   // [b,h,s,d]

// transposed weights: [N_rows, K] fp16 (w13: rows interleaved w1/w3)
__device__ __half g_wqkv[3072*1024];
__device__ __half g_wot [1024*1024];
__device__ __half g_w13 [(size_t)8192*1024];
__device__ __half g_w2t [(size_t)1024*4096];

// ==================== helpers ====================
__device__ __forceinline__ uint32_t smem_u32(const void* p) {
    return (uint32_t)__cvta_generic_to_shared(p);
}
__device__ __forceinline__ void ldsm4(uint32_t* r, uint32_t a) {
    asm volatile("ldmatrix.sync.aligned.m8n8.x4.shared.b16 {%0,%1,%2,%3}, [%4];"
                 : "=r"(r[0]), "=r"(r[1]), "=r"(r[2]), "=r"(r[3]) : "r"(a));
}
__device__ __forceinline__ void ldsm4t(uint32_t* r, uint32_t a) {
    asm volatile("ldmatrix.sync.aligned.m8n8.x4.trans.shared.b16 {%0,%1,%2,%3}, [%4];"
                 : "=r"(r[0]), "=r"(r[1]), "=r"(r[2]), "=r"(r[3]) : "r"(a));
}
__device__ __forceinline__ void mma16816h(float* d, const uint32_t* a, const uint32_t* b) {
    asm volatile("mma.sync.aligned.m16n8k16.row.col.f32.f16.f16.f32 "
                 "{%0,%1,%2,%3}, {%4,%5,%6,%7}, {%8,%9}, {%0,%1,%2,%3};"
                 : "+f"(d[0]), "+f"(d[1]), "+f"(d[2]), "+f"(d[3])
                 : "r"(a[0]), "r"(a[1]), "r"(a[2]), "r"(a[3]), "r"(b[0]), "r"(b[1]));
}
__device__ __forceinline__ void cpa16(uint32_t s, const void* g) {
    asm volatile("cp.async.cg.shared.global [%0], [%1], 16;" :: "r"(s), "l"(g) : "memory");
}
__device__ __forceinline__ uint32_t packh(float a, float b) {
    __half2 t = __floats2half2_rn(a, b);   // a in low half
    return *(uint32_t*)&t;
}

// smem tile geometry for hgemm: 128 rows x 64 halves, pitch 72 halves (144B)
#define LK2 72
#define TILE2B (128*LK2*2)      // 18432 B per tile
#define NSTG 3

// ==================== HMMA fp16 GEMM: C = A@B^T (+X) ====================
// MODE 0: C fp32   MODE 1: C = acc + X (fp32)   MODE 2: swiglu pairs -> O fp16
// MODE 3: O fp16 raw
template<int MODE>
__global__ void __launch_bounds__(256, 2)
hgemm(const __half* __restrict__ A, const __half* __restrict__ B,
      float* __restrict__ C, const float* __restrict__ X,
      __half* __restrict__ O, int K, int ldc) {
    extern __shared__ char smem[];
    uint32_t s0 = smem_u32(smem);

    int tid = threadIdx.x, lane = tid & 31, wid = tid >> 5;
    int m0 = blockIdx.y * 128, n0 = blockIdx.x * 128;
    int wm = wid & 1, wn = wid >> 1;     // 2 x 4 warps; warp tile 64(M) x 32(N)

    float acc[4][4][4];
    #pragma unroll
    for (int i = 0; i < 4; i++)
        #pragma unroll
        for (int j = 0; j < 4; j++)
            #pragma unroll
            for (int e = 0; e < 4; e++) acc[i][j][e] = 0.f;

    auto issue = [&](int slot, int kc) {
        uint32_t sa = s0 + slot * 2 * TILE2B;
        uint32_t sb = sa + TILE2B;
        #pragma unroll
        for (int t = 0; t < 4; ++t) {
            int idx = tid + t * 256;            // 1024 chunks per tile
            int r = idx >> 3, c = (idx & 7) * 8;
            cpa16(sa + (r * LK2 + c) * 2, A + (size_t)(m0 + r) * K + kc + c);
            cpa16(sb + (r * LK2 + c) * 2, B + (size_t)(n0 + r) * K + kc + c);
        }
        asm volatile("cp.async.commit_group;" ::: "memory");
    };

    int arow = wm * 64 + (lane & 15);
    int acol = (lane & 16) ? 8 : 0;
    int brow = wn * 32 + (lane & 7) + ((lane & 16) ? 8 : 0);
    int bcol = (lane & 8) ? 8 : 0;

    int NC = K >> 6;
    issue(0, 0);
    issue(1, 64);

    for (int c = 0; c < NC; ++c) {
        if (c + 1 < NC) {
            asm volatile("cp.async.wait_group 1;" ::: "memory");
        } else {
            asm volatile("cp.async.wait_group 0;" ::: "memory");
        }
        __syncthreads();      // data of stage c ready AND slot (c-1) free

        int slot = c % NSTG;
        uint32_t sA = s0 + slot * 2 * TILE2B;
        uint32_t sB = sA + TILE2B;

        #pragma unroll
        for (int ks = 0; ks < 4; ++ks) {
            uint32_t bf[2][4];
            #pragma unroll
            for (int ni2 = 0; ni2 < 2; ++ni2)
                ldsm4(bf[ni2], sB + ((brow + ni2 * 16) * LK2 + bcol + ks * 16) * 2);
            #pragma unroll
            for (int mi = 0; mi < 4; ++mi) {
                uint32_t af[4];
                ldsm4(af, sA + ((arow + mi * 16) * LK2 + acol + ks * 16) * 2);
                #pragma unroll
                for (int n8 = 0; n8 < 4; ++n8)
                    mma16816h(acc[mi][n8], af, &bf[n8 >> 1][(n8 & 1) * 2]);
            }
        }

        if (c + 2 < NC) issue((c + 2) % NSTG, (c + 2) << 6);
    }

    int rbase = m0 + wm * 64 + (lane >> 2);
    #pragma unroll
    for (int mi = 0; mi < 4; ++mi) {
        #pragma unroll
        for (int half = 0; half < 2; ++half) {
            int row = rbase + mi * 16 + half * 8;
            if (MODE == 2) {
                // swiglu: acc pairs (a,b) at cols (2p, 2p+1) -> g[row][p]
                int pldc = ldc >> 1;
                int pbase = (n0 >> 1) + wn * 16 + (lane & 3);
                #pragma unroll
                for (int n8 = 0; n8 < 4; ++n8) {
                    float a = acc[mi][n8][half * 2 + 0];
                    float b = acc[mi][n8][half * 2 + 1];
                    float g = a / (1.0f + expf(-a)) * b;
                    O[(size_t)row * pldc + pbase + n8 * 4] = __float2half(g);
                }
            } else if (MODE == 3) {
                int cbase = n0 + wn * 32 + (lane & 3) * 2;
                __half* orow = O + (size_t)row * ldc;
                #pragma unroll
                for (int n8 = 0; n8 < 4; ++n8) {
                    int col = cbase + n8 * 8;
                    *(uint32_t*)(orow + col) =
                        packh(acc[mi][n8][half * 2 + 0], acc[mi][n8][half * 2 + 1]);
                }
            } else {
                int cbase = n0 + wn * 32 + (lane & 3) * 2;
                float* crow = C + (size_t)row * ldc;
                const float* xrow = (MODE == 1) ? X + (size_t)row * ldc : nullptr;
                #pragma unroll
                for (int n8 = 0; n8 < 4; ++n8) {
                    int col = cbase + n8 * 8;
                    float2 v;
                    v.x = acc[mi][n8][half * 2 + 0];
                    v.y = acc[mi][n8][half * 2 + 1];
                    if (MODE == 1) {
                        float2 xv = *(const float2*)(xrow + col);
                        v.x += xv.x; v.y += xv.y;
                    }
                    *(float2*)(crow + col) = v;
                }
            }
        }
    }
}

// ==================== rope table (standalone tiny launch) ====================
__global__ void build_tab(float2* __restrict__ tab) {
    int i = blockIdx.x * 256 + threadIdx.x;     // S*32 entries
    int s = i >> 5, dd = i & 31;
    double inv = exp(-(double)dd * (log(10000.0) / 32.0));
    double ang = (double)s * inv;
    tab[i] = make_float2((float)cos(ang), (float)sin(ang));
}

// ==================== weight prep: K32 x N128 tiles ====================
// ids (blockIdx.x + base):
// phase A [0,768): [0,256)=wq [256,512)=wk [512,768)=wv
// phase B [768,4096): [768,1024)=wo [1024,2048)=w1 [2048,3072)=w3 [3072,4096)=w2
__global__ void prep_all(const float* __restrict__ wq, const float* __restrict__ wk,
                         const float* __restrict__ wv, const float* __restrict__ wo,
                         const float* __restrict__ w1, const float* __restrict__ w2,
                         const float* __restrict__ w3,
                         __half* __restrict__ wqkv, __half* __restrict__ wot,
                         __half* __restrict__ w13,  __half* __restrict__ w2t,
                         int base) {
    int id = blockIdx.x + base;
    int tx = threadIdx.x, ty = threadIdx.y;     // 32 x 8
    int tid = ty * 32 + tx;

    const float* Wp; __half* dst;
    int N, nbn, roff = 0, ldo, inter = 0, odd = 0, local;
    if (id < 256)        { Wp = wq; dst = wqkv; N = 1024; nbn = 8;  roff = 0;    ldo = 1024; local = id; }
    else if (id < 512)   { Wp = wk; dst = wqkv; N = 1024; nbn = 8;  roff = 1024; ldo = 1024; local = id - 256; }
    else if (id < 768)   { Wp = wv; dst = wqkv; N = 1024; nbn = 8;  roff = 2048; ldo = 1024; local = id - 512; }
    else if (id < 1024)  { Wp = wo; dst = wot;  N = 1024; nbn = 8;  roff = 0;    ldo = 1024; local = id - 768; }
    else if (id < 2048)  { Wp = w1; dst = w13;  N = 4096; nbn = 32; ldo = 1024; inter = 1; odd = 0; local = id - 1024; }
    else if (id < 3072)  { Wp = w3; dst = w13;  N = 4096; nbn = 32; ldo = 1024; inter = 1; odd = 1; local = id - 2048; }
    else                 { Wp = w2; dst = w2t;  N = 1024; nbn = 8;  ldo = 4096; local = id - 3072; }

    __shared__ float t[32][129];
    int n0 = (local % nbn) * 128, k0 = (local / nbn) * 32;

    #pragma unroll
    for (int i = 0; i < 32; i += 8) {
        float4 v = *(const float4*)(Wp + (size_t)(k0 + ty + i) * N + n0 + tx * 4);
        t[ty + i][tx * 4 + 0] = v.x;
        t[ty + i][tx * 4 + 1] = v.y;
        t[ty + i][tx * 4 + 2] = v.z;
        t[ty + i][tx * 4 + 3] = v.w;
    }
    __syncthreads();

    int kk = tid & 15, nn = tid >> 4;
    #pragma unroll
    for (int ni = 0; ni < 8; ++ni) {
        int nl = nn + ni * 16;
        int n = n0 + nl;
        int row = inter ? (2 * n + odd) : (roff + n);
        uint32_t pk = packh(t[2 * kk][nl], t[2 * kk + 1][nl]);
        *(uint32_t*)(dst + (size_t)row * ldo + k0 + 2 * kk) = pk;
    }
}

// ==================== LayerNorm -> fp16 ====================
__global__ void ln_h(const float* __restrict__ x, const float* __restrict__ g,
                     const float* __restrict__ b, __half* __restrict__ y) {
    int t = blockIdx.x, tid = threadIdx.x;
    const float4* xr = (const float4*)(x + (size_t)t * D_);
    float4 xv = xr[tid];
    __shared__ float rbuf[8];
    __shared__ float s_mean, s_rstd;

    float s = xv.x + xv.y + xv.z + xv.w;
    #pragma unroll
    for (int o = 16; o; o >>= 1) s += __shfl_xor_sync(~0u, s, o);
    if ((tid & 31) == 0) rbuf[tid >> 5] = s;
    __syncthreads();
    if (tid == 0) {
        float m = 0.f;
        #pragma unroll
        for (int i = 0; i < 8; i++) m += rbuf[i];
        s_mean = m * (1.0f / D_);
    }
    __syncthreads();
    float mean = s_mean;
    float dx = xv.x - mean, dy = xv.y - mean, dz = xv.z - mean, dw = xv.w - mean;
    float s2 = dx*dx + dy*dy + dz*dz + dw*dw;
    #pragma unroll
    for (int o = 16; o; o >>= 1) s2 += __shfl_xor_sync(~0u, s2, o);
    if ((tid & 31) == 0) rbuf[tid >> 5] = s2;
    __syncthreads();
    if (tid == 0) {
        float v = 0.f;
        #pragma unroll
        for (int i = 0; i < 8; i++) v += rbuf[i];
        s_rstd = rsqrtf(v * (1.0f / D_) + 1e-6f);
    }
    __syncthreads();
    float rstd = s_rstd;
    const float4 gv = ((const float4*)g)[tid];
    const float4 bv = ((const float4*)b)[tid];
    size_t base = (size_t)t * D_ + tid * 4;
    y[base+0] = __float2half(dx * rstd * gv.x + bv.x);
    y[base+1] = __float2half(dy * rstd * gv.y + bv.y);
    y[base+2] = __float2half(dz * rstd * gv.z + bv.z);
    y[base+3] = __float2half(dw * rstd * gv.w + bv.w);
}

// ==================== RoPE + scatter: qkvh fp16 -> q/k/v fp16 [b,h,s,d] ====================
__global__ void rope_cvt(const __half* __restrict__ qkv, const float2* __restrict__ tab,
                         __half* __restrict__ qh, __half* __restrict__ kh,
                         __half* __restrict__ vh) {
    int t = blockIdx.x;                 // token
    int tid = threadIdx.x;              // 128
    int b = t / S_, s = t & (S_ - 1);
    int d = tid & 63;
    float2 cs = tab[s * 32 + (d & 31)];
    float c = cs.x, sn = cs.y;
    const __half* row = qkv + (size_t)t * QKV_LD;

    #pragma unroll
    for (int hh = 0; hh < 8; ++hh) {
        int h = hh * 2 + (tid >> 6);
        size_t oidx = ((size_t)(b * H_ + h) * S_ + s) * HD_ + d;
        {
            float x1 = __half2float(row[h * 64 + d]);
            float x2 = __half2float(row[h * 64 + (d ^ 32)]);
            float o = (d < 32) ? (x1 * c - x2 * sn) : (x1 * c + x2 * sn);
            qh[oidx] = __float2half(o * 0.125f);
        }
        {
            float x1 = __half2float(row[1024 + h * 64 + d]);
            float x2 = __half2float(row[1024 + h * 64 + (d ^ 32)]);
            float o = (d < 32) ? (x1 * c - x2 * sn) : (x1 * c + x2 * sn);
            kh[oidx] = __float2half(o);
        }
        vh[oidx] = row[2048 + h * 64 + d];
    }
}

// ==================== flash attention (HMMA fp16, sliding window 256) ====================
#define LK_ 72
__global__ void __launch_bounds__(256, 2)
attn_mma(const __half* __restrict__ qh, const __half* __restrict__ kh,
         const __half* __restrict__ vh, __half* __restrict__ ch) {
    extern __shared__ char smem[];
    uint32_t sQ = smem_u32(smem);
    uint32_t sK = sQ + 128 * LK_ * 2;
    uint32_t sV = sK + 128 * LK_ * 2;

    int q0 = blockIdx.x * 128;
    int h = blockIdx.y, bi = blockIdx.z;
    int tid = threadIdx.x, lane = tid & 31, w = tid >> 5;
    size_t bh = ((size_t)(bi * H_ + h)) * S_;

    for (int i = tid; i < 128 * 8; i += 256) {
        int r = i >> 3, c8 = (i & 7) * 8;
        uint4 v = *(const uint4*)(qh + (bh + q0 + r) * HD_ + c8);
        *(uint4*)(smem + (r * LK_ + c8) * 2) = v;
    }
    __syncthreads();

    uint32_t qf[4][4];
    {
        int ar = w * 16 + (lane & 15);
        int ac = (lane & 16) ? 8 : 0;
        #pragma unroll
        for (int kc = 0; kc < 4; ++kc)
            ldsm4(qf[kc], sQ + (ar * LK_ + ac + kc * 16) * 2);
    }

    float O[8][4];
    #pragma unroll
    for (int i = 0; i < 8; i++) { O[i][0]=0; O[i][1]=0; O[i][2]=0; O[i][3]=0; }
    float rm0 = -1e30f, rm1 = -1e30f, l0 = 0.f, l1 = 0.f;

    int g = lane >> 2, tq = lane & 3;
    int qrow0 = q0 + w * 16 + g;

    #pragma unroll
    for (int it = 0; it < 3; ++it) {
        int ord = 2 - it;                    // diagonal tile first
        int kbase = q0 - 256 + ord * 128;
        if (kbase + 128 <= 0) continue;

        __syncthreads();
        for (int i = tid; i < 128 * 8; i += 256) {
            int r = i >> 3, c8 = (i & 7) * 8;
            int krow = kbase + r; if (krow < 0) krow = 0;
            uint4 kv = *(const uint4*)(kh + (bh + krow) * HD_ + c8);
            uint4 vv = *(const uint4*)(vh + (bh + krow) * HD_ + c8);
            *(uint4*)(smem + (128 * LK_ + r * LK_ + c8) * 2) = kv;
            *(uint4*)(smem + (256 * LK_ + r * LK_ + c8) * 2) = vv;
        }
        __syncthreads();

        float sf[16][4];
        {
            int br = (lane & 7) + ((lane & 16) ? 8 : 0);
            int bc = (lane & 8) ? 8 : 0;
            #pragma unroll
            for (int ni2 = 0; ni2 < 8; ++ni2) {
                float s4[8] = {0,0,0,0,0,0,0,0};
                #pragma unroll
                for (int kc = 0; kc < 4; ++kc) {
                    uint32_t kf[4];
                    ldsm4(kf, sK + ((ni2 * 16 + br) * LK_ + bc + kc * 16) * 2);
                    mma16816h(s4,     qf[kc], kf + 0);
                    mma16816h(s4 + 4, qf[kc], kf + 2);
                }
                #pragma unroll
                for (int e = 0; e < 4; e++) { sf[2*ni2][e] = s4[e]; sf[2*ni2+1][e] = s4[4+e]; }
            }
        }

        float tm0 = -1e30f, tm1 = -1e30f;
        #pragma unroll
        for (int ni = 0; ni < 16; ++ni) {
            int colb = kbase + ni * 8 + tq * 2;
            #pragma unroll
            for (int e = 0; e < 2; ++e) {
                int col = colb + e;
                int r0 = qrow0 - col, r1 = qrow0 + 8 - col;
                if (!(col >= 0 && r0 >= 0 && r0 < W_)) sf[ni][e]     = -1e30f;
                if (!(col >= 0 && r1 >= 0 && r1 < W_)) sf[ni][2 + e] = -1e30f;
                tm0 = fmaxf(tm0, sf[ni][e]);
                tm1 = fmaxf(tm1, sf[ni][2 + e]);
            }
        }
        tm0 = fmaxf(tm0, __shfl_xor_sync(~0u, tm0, 1));
        tm0 = fmaxf(tm0, __shfl_xor_sync(~0u, tm0, 2));
        tm1 = fmaxf(tm1, __shfl_xor_sync(~0u, tm1, 1));
        tm1 = fmaxf(tm1, __shfl_xor_sync(~0u, tm1, 2));

        float m0 = fmaxf(rm0, tm0), m1 = fmaxf(rm1, tm1);
        float a0 = __expf(rm0 - m0), a1 = __expf(rm1 - m1);
        rm0 = m0; rm1 = m1;
        #pragma unroll
        for (int nd = 0; nd < 8; ++nd) {
            O[nd][0] *= a0; O[nd][1] *= a0; O[nd][2] *= a1; O[nd][3] *= a1;
        }
        float rs0 = 0.f, rs1 = 0.f;
        #pragma unroll
        for (int ni = 0; ni < 16; ++ni) {
            float p0 = __expf(sf[ni][0] - m0);
            float p1 = __expf(sf[ni][1] - m0);
            float p2 = __expf(sf[ni][2] - m1);
            float p3 = __expf(sf[ni][3] - m1);
            sf[ni][0] = p0; sf[ni][1] = p1; sf[ni][2] = p2; sf[ni][3] = p3;
            rs0 += p0 + p1; rs1 += p2 + p3;
        }
        rs0 += __shfl_xor_sync(~0u, rs0, 1); rs0 += __shfl_xor_sync(~0u, rs0, 2);
        rs1 += __shfl_xor_sync(~0u, rs1, 1); rs1 += __shfl_xor_sync(~0u, rs1, 2);
        l0 = l0 * a0 + rs0;
        l1 = l1 * a1 + rs1;

        #pragma unroll
        for (int j = 0; j < 8; ++j) {
            uint32_t aP[4];
            aP[0] = packh(sf[2*j][0],   sf[2*j][1]);
            aP[1] = packh(sf[2*j][2],   sf[2*j][3]);
            aP[2] = packh(sf[2*j+1][0], sf[2*j+1][1]);
            aP[3] = packh(sf[2*j+1][2], sf[2*j+1][3]);
            int sel = lane >> 3;
            int vr = 16 * j + (lane & 7) + ((sel & 1) * 8);
            #pragma unroll
            for (int np = 0; np < 4; ++np) {
                uint32_t vf[4];
                ldsm4t(vf, sV + (vr * LK_ + np * 16 + ((sel >> 1) * 8)) * 2);
                mma16816h(O[2*np],     aP, vf + 0);
                mma16816h(O[2*np + 1], aP, vf + 2);
            }
        }
    }

    float i0 = 1.0f / l0, i1 = 1.0f / l1;
    size_t r0o = ((size_t)(bi * S_ + qrow0)) * D_ + h * HD_;
    size_t r1o = ((size_t)(bi * S_ + qrow0 + 8)) * D_ + h * HD_;
    #pragma unroll
    for (int nd = 0; nd < 8; ++nd) {
        int col = nd * 8 + tq * 2;
        #pragma unroll
        for (int e = 0; e < 2; ++e) {
            ch[r0o + col + e] = __float2half(O[nd][e] * i0);
            ch[r1o + col + e] = __float2half(O[nd][2 + e] * i1);
        }
    }
}

// ==================== launch ====================
extern "C" void kernel_launch(void* const* d_in, const int* in_sizes, int n_in,
                              void* d_out, int out_size) {
    const float* hidden = (const float*)d_in[0];
    const float* wq = (const float*)d_in[1];
    const float* wk = (const float*)d_in[2];
    const float* wv = (const float*)d_in[3];
    const float* wo = (const float*)d_in[4];
    const float* w1 = (const float*)d_in[5];
    const float* w2 = (const float*)d_in[6];
    const float* w3 = (const float*)d_in[7];
    const float* ln1_g = (const float*)d_in[8];
    const float* ln1_b = (const float*)d_in[9];
    const float* ln2_g = (const float*)d_in[10];
    const float* ln2_b = (const float*)d_in[11];
    float* out = (float*)d_out;

    float *hid; float2* tab;
    __half *qkvh, *xa, *ca, *gg, *qh, *kh, *vh, *wqkv, *wot, *w13, *w2t;
    cudaGetSymbolAddress((void**)&hid, g_hid);
    cudaGetSymbolAddress((void**)&tab, g_tab);
    cudaGetSymbolAddress((void**)&qkvh, g_qkvh);
    cudaGetSymbolAddress((void**)&xa, g_xa);
    cudaGetSymbolAddress((void**)&ca, g_ca);
    cudaGetSymbolAddress((void**)&gg, g_g);
    cudaGetSymbolAddress((void**)&qh, g_qh);
    cudaGetSymbolAddress((void**)&kh, g_kh);
    cudaGetSymbolAddress((void**)&vh, g_vh);
    cudaGetSymbolAddress((void**)&wqkv, g_wqkv);
    cudaGetSymbolAddress((void**)&wot, g_wot);
    cudaGetSymbolAddress((void**)&w13, g_w13);
    cudaGetSymbolAddress((void**)&w2t, g_w2t);

    const int SMEM_G = 2 * NSTG * TILE2B;      // 110592 B (3 stages x A,B)
    cudaFuncSetAttribute(hgemm<1>, cudaFuncAttributeMaxDynamicSharedMemorySize, SMEM_G);
    cudaFuncSetAttribute(hgemm<2>, cudaFuncAttributeMaxDynamicSharedMemorySize, SMEM_G);
    cudaFuncSetAttribute(hgemm<3>, cudaFuncAttributeMaxDynamicSharedMemorySize, SMEM_G);
    const int SMEM_ATT = 3 * 128 * LK_ * 2;   // 55296 B
    cudaFuncSetAttribute(attn_mma, cudaFuncAttributeMaxDynamicSharedMemorySize, SMEM_ATT);

    // persistent side stream + events
    static cudaStream_t s2 = nullptr;
    static cudaEvent_t eFork = nullptr, eQkvW = nullptr, eTab = nullptr, eRestW = nullptr;
    if (s2 == nullptr) {
        cudaStreamCreateWithFlags(&s2, cudaStreamNonBlocking);
        cudaEventCreateWithFlags(&eFork,  cudaEventDisableTiming);
        cudaEventCreateWithFlags(&eQkvW,  cudaEventDisableTiming);
        cudaEventCreateWithFlags(&eTab,   cudaEventDisableTiming);
        cudaEventCreateWithFlags(&eRestW, cudaEventDisableTiming);
    }

    // fork: weight prep on side stream
    cudaEventRecord(eFork, 0);
    cudaStreamWaitEvent(s2, eFork, 0);
    // phase A: wq/wk/wv only (768 blocks) — minimal pre-QKV latency
    prep_all<<<768, dim3(32, 8), 0, s2>>>(wq, wk, wv, wo, w1, w2, w3,
                                          wqkv, wot, w13, w2t, 0);
    cudaEventRecord(eQkvW, s2);
    // rope table (tiny) — ready long before rope_cvt needs it
    build_tab<<<(S_ * 32) / 256, 256, 0, s2>>>(tab);
    cudaEventRecord(eTab, s2);
    // phase B: wo/w13/w2 — overlaps QKV GEMM + attention
    prep_all<<<3328, dim3(32, 8), 0, s2>>>(wq, wk, wv, wo, w1, w2, w3,
                                           wqkv, wot, w13, w2t, 768);
    cudaEventRecord(eRestW, s2);

    // --- attention sub-block (main stream) ---
    ln_h<<<TOK, 256>>>(hidden, ln1_g, ln1_b, xa);
    cudaStreamWaitEvent(0, eQkvW, 0);
    hgemm<3><<<dim3(24, 32), 256, SMEM_G>>>(xa, wqkv, nullptr, nullptr, qkvh, 1024, QKV_LD);
    cudaStreamWaitEvent(0, eTab, 0);
    rope_cvt<<<TOK, 128>>>(qkvh, tab, qh, kh, vh);
    attn_mma<<<dim3(S_ / 128, H_, B_), 256, SMEM_ATT>>>(qh, kh, vh, ca);
    cudaStreamWaitEvent(0, eRestW, 0);     // wo/w13/w2 ready (hidden under QKV+attn)
    hgemm<1><<<dim3(8, 32), 256, SMEM_G>>>(ca, wot, hid, hidden, nullptr, 1024, D_);

    // --- SwiGLU MLP sub-block ---
    ln_h<<<TOK, 256>>>(hid, ln2_g, ln2_b, xa);
    hgemm<2><<<dim3(64, 32), 256, SMEM_G>>>(xa, w13, nullptr, nullptr, gg, 1024, 8192);
    hgemm<1><<<dim3(8, 32), 256, SMEM_G>>>(gg, w2t, out, hid, nullptr, 4096, D_);
}

// round 17
// speedup vs baseline: 1.0841x; 1.0050x over previous
#include <cuda_runtime.h>
#include <cuda_fp16.h>
#include <math.h>
#include <stdint.h>

#define B_  2
#define S_  2048
#define D_  1024
#define H_  16
#define HD_ 64
#define I_  4096
#define W_  256
#define TOK (B_*S_)
#define QKV_LD 3072

// ==================== scratch (__device__ globals; no allocs) ====================
__device__ float g_hid[TOK*D_];
__device__ float2 g_tab[S_*32];

__device__ __half g_qkvh[(size_t)TOK*QKV_LD];
__device__ __half g_xa[TOK*D_];
__device__ __half g_ca[TOK*D_];
__device__ __half g_g [(size_t)TOK*I_];
__device__ __half g_qh[TOK*D_];   // [b,h,s,d] scaled by 0.125, roped
__device__ __half g_kh[TOK*D_];   // [b,h,s,d] roped
__device__ __half g_vh[TOK*D_];   // [b,h,s,d]

// transposed weights: [N_rows, K] fp16 (w13: rows interleaved w1/w3)
__device__ __half g_wqkv[3072*1024];
__device__ __half g_wot [1024*1024];
__device__ __half g_w13 [(size_t)8192*1024];
__device__ __half g_w2t [(size_t)1024*4096];

// ==================== helpers ====================
__device__ __forceinline__ uint32_t smem_u32(const void* p) {
    return (uint32_t)__cvta_generic_to_shared(p);
}
__device__ __forceinline__ void ldsm4(uint32_t* r, uint32_t a) {
    asm volatile("ldmatrix.sync.aligned.m8n8.x4.shared.b16 {%0,%1,%2,%3}, [%4];"
                 : "=r"(r[0]), "=r"(r[1]), "=r"(r[2]), "=r"(r[3]) : "r"(a));
}
__device__ __forceinline__ void ldsm4t(uint32_t* r, uint32_t a) {
    asm volatile("ldmatrix.sync.aligned.m8n8.x4.trans.shared.b16 {%0,%1,%2,%3}, [%4];"
                 : "=r"(r[0]), "=r"(r[1]), "=r"(r[2]), "=r"(r[3]) : "r"(a));
}
__device__ __forceinline__ void mma16816h(float* d, const uint32_t* a, const uint32_t* b) {
    asm volatile("mma.sync.aligned.m16n8k16.row.col.f32.f16.f16.f32 "
                 "{%0,%1,%2,%3}, {%4,%5,%6,%7}, {%8,%9}, {%0,%1,%2,%3};"
                 : "+f"(d[0]), "+f"(d[1]), "+f"(d[2]), "+f"(d[3])
                 : "r"(a[0]), "r"(a[1]), "r"(a[2]), "r"(a[3]), "r"(b[0]), "r"(b[1]));
}
__device__ __forceinline__ void cpa16(uint32_t s, const void* g) {
    asm volatile("cp.async.cg.shared.global [%0], [%1], 16;" :: "r"(s), "l"(g) : "memory");
}
__device__ __forceinline__ uint32_t packh(float a, float b) {
    __half2 t = __floats2half2_rn(a, b);   // a in low half
    return *(uint32_t*)&t;
}

// smem tile geometry for hgemm: 128 rows x 64 halves, pitch 72 halves (144B)
#define LK2 72
#define TILE2B (128*LK2*2)      // 18432 B per tile
#define NSTG 3

// ==================== HMMA fp16 GEMM: C = A@B^T (+X) ====================
// MODE 0: C fp32   MODE 1: C = acc + X (fp32)   MODE 2: swiglu pairs -> O fp16
// MODE 3: O fp16 raw
template<int MODE>
__global__ void __launch_bounds__(256, 2)
hgemm(const __half* __restrict__ A, const __half* __restrict__ B,
      float* __restrict__ C, const float* __restrict__ X,
      __half* __restrict__ O, int K, int ldc) {
    extern __shared__ char smem[];
    uint32_t s0 = smem_u32(smem);

    int tid = threadIdx.x, lane = tid & 31, wid = tid >> 5;
    int m0 = blockIdx.y * 128, n0 = blockIdx.x * 128;
    int wm = wid & 1, wn = wid >> 1;     // 2 x 4 warps; warp tile 64(M) x 32(N)

    float acc[4][4][4];
    #pragma unroll
    for (int i = 0; i < 4; i++)
        #pragma unroll
        for (int j = 0; j < 4; j++)
            #pragma unroll
            for (int e = 0; e < 4; e++) acc[i][j][e] = 0.f;

    auto issue = [&](int slot, int kc) {
        uint32_t sa = s0 + slot * 2 * TILE2B;
        uint32_t sb = sa + TILE2B;
        #pragma unroll
        for (int t = 0; t < 4; ++t) {
            int idx = tid + t * 256;            // 1024 chunks per tile
            int r = idx >> 3, c = (idx & 7) * 8;
            cpa16(sa + (r * LK2 + c) * 2, A + (size_t)(m0 + r) * K + kc + c);
            cpa16(sb + (r * LK2 + c) * 2, B + (size_t)(n0 + r) * K + kc + c);
        }
        asm volatile("cp.async.commit_group;" ::: "memory");
    };

    int arow = wm * 64 + (lane & 15);
    int acol = (lane & 16) ? 8 : 0;
    int brow = wn * 32 + (lane & 7) + ((lane & 16) ? 8 : 0);
    int bcol = (lane & 8) ? 8 : 0;

    int NC = K >> 6;
    issue(0, 0);
    issue(1, 64);

    for (int c = 0; c < NC; ++c) {
        if (c + 1 < NC) {
            asm volatile("cp.async.wait_group 1;" ::: "memory");
        } else {
            asm volatile("cp.async.wait_group 0;" ::: "memory");
        }
        __syncthreads();      // data of stage c ready AND slot (c-1) free

        int slot = c % NSTG;
        uint32_t sA = s0 + slot * 2 * TILE2B;
        uint32_t sB = sA + TILE2B;

        #pragma unroll
        for (int ks = 0; ks < 4; ++ks) {
            uint32_t bf[2][4];
            #pragma unroll
            for (int ni2 = 0; ni2 < 2; ++ni2)
                ldsm4(bf[ni2], sB + ((brow + ni2 * 16) * LK2 + bcol + ks * 16) * 2);
            #pragma unroll
            for (int mi = 0; mi < 4; ++mi) {
                uint32_t af[4];
                ldsm4(af, sA + ((arow + mi * 16) * LK2 + acol + ks * 16) * 2);
                #pragma unroll
                for (int n8 = 0; n8 < 4; ++n8)
                    mma16816h(acc[mi][n8], af, &bf[n8 >> 1][(n8 & 1) * 2]);
            }
        }

        if (c + 2 < NC) issue((c + 2) % NSTG, (c + 2) << 6);
    }

    int rbase = m0 + wm * 64 + (lane >> 2);
    #pragma unroll
    for (int mi = 0; mi < 4; ++mi) {
        #pragma unroll
        for (int half = 0; half < 2; ++half) {
            int row = rbase + mi * 16 + half * 8;
            if (MODE == 2) {
                // swiglu: acc pairs (a,b) at cols (2p, 2p+1) -> g[row][p]
                int pldc = ldc >> 1;
                int pbase = (n0 >> 1) + wn * 16 + (lane & 3);
                #pragma unroll
                for (int n8 = 0; n8 < 4; ++n8) {
                    float a = acc[mi][n8][half * 2 + 0];
                    float b = acc[mi][n8][half * 2 + 1];
                    float g = a / (1.0f + expf(-a)) * b;
                    O[(size_t)row * pldc + pbase + n8 * 4] = __float2half(g);
                }
            } else if (MODE == 3) {
                int cbase = n0 + wn * 32 + (lane & 3) * 2;
                __half* orow = O + (size_t)row * ldc;
                #pragma unroll
                for (int n8 = 0; n8 < 4; ++n8) {
                    int col = cbase + n8 * 8;
                    *(uint32_t*)(orow + col) =
                        packh(acc[mi][n8][half * 2 + 0], acc[mi][n8][half * 2 + 1]);
                }
            } else {
                int cbase = n0 + wn * 32 + (lane & 3) * 2;
                float* crow = C + (size_t)row * ldc;
                const float* xrow = (MODE == 1) ? X + (size_t)row * ldc : nullptr;
                #pragma unroll
                for (int n8 = 0; n8 < 4; ++n8) {
                    int col = cbase + n8 * 8;
                    float2 v;
                    v.x = acc[mi][n8][half * 2 + 0];
                    v.y = acc[mi][n8][half * 2 + 1];
                    if (MODE == 1) {
                        float2 xv = *(const float2*)(xrow + col);
                        v.x += xv.x; v.y += xv.y;
                    }
                    *(float2*)(crow + col) = v;
                }
            }
        }
    }
}

// ==================== rope table (standalone tiny launch) ====================
__global__ void build_tab(float2* __restrict__ tab) {
    int i = blockIdx.x * 256 + threadIdx.x;     // S*32 entries
    int s = i >> 5, dd = i & 31;
    double inv = exp(-(double)dd * (log(10000.0) / 32.0));
    double ang = (double)s * inv;
    tab[i] = make_float2((float)cos(ang), (float)sin(ang));
}

// ==================== weight prep: K32 x N128 tiles ====================
// ids (blockIdx.x + base):
// phase A [0,768): [0,256)=wq [256,512)=wk [512,768)=wv
// phase B [768,4096): [768,1024)=wo [1024,2048)=w1 [2048,3072)=w3 [3072,4096)=w2
__global__ void prep_all(const float* __restrict__ wq, const float* __restrict__ wk,
                         const float* __restrict__ wv, const float* __restrict__ wo,
                         const float* __restrict__ w1, const float* __restrict__ w2,
                         const float* __restrict__ w3,
                         __half* __restrict__ wqkv, __half* __restrict__ wot,
                         __half* __restrict__ w13,  __half* __restrict__ w2t,
                         int base) {
    int id = blockIdx.x + base;
    int tx = threadIdx.x, ty = threadIdx.y;     // 32 x 8
    int tid = ty * 32 + tx;

    const float* Wp; __half* dst;
    int N, nbn, roff = 0, ldo, inter = 0, odd = 0, local;
    if (id < 256)        { Wp = wq; dst = wqkv; N = 1024; nbn = 8;  roff = 0;    ldo = 1024; local = id; }
    else if (id < 512)   { Wp = wk; dst = wqkv; N = 1024; nbn = 8;  roff = 1024; ldo = 1024; local = id - 256; }
    else if (id < 768)   { Wp = wv; dst = wqkv; N = 1024; nbn = 8;  roff = 2048; ldo = 1024; local = id - 512; }
    else if (id < 1024)  { Wp = wo; dst = wot;  N = 1024; nbn = 8;  roff = 0;    ldo = 1024; local = id - 768; }
    else if (id < 2048)  { Wp = w1; dst = w13;  N = 4096; nbn = 32; ldo = 1024; inter = 1; odd = 0; local = id - 1024; }
    else if (id < 3072)  { Wp = w3; dst = w13;  N = 4096; nbn = 32; ldo = 1024; inter = 1; odd = 1; local = id - 2048; }
    else                 { Wp = w2; dst = w2t;  N = 1024; nbn = 8;  ldo = 4096; local = id - 3072; }

    __shared__ float t[32][129];
    int n0 = (local % nbn) * 128, k0 = (local / nbn) * 32;

    #pragma unroll
    for (int i = 0; i < 32; i += 8) {
        float4 v = *(const float4*)(Wp + (size_t)(k0 + ty + i) * N + n0 + tx * 4);
        t[ty + i][tx * 4 + 0] = v.x;
        t[ty + i][tx * 4 + 1] = v.y;
        t[ty + i][tx * 4 + 2] = v.z;
        t[ty + i][tx * 4 + 3] = v.w;
    }
    __syncthreads();

    int kk = tid & 15, nn = tid >> 4;
    #pragma unroll
    for (int ni = 0; ni < 8; ++ni) {
        int nl = nn + ni * 16;
        int n = n0 + nl;
        int row = inter ? (2 * n + odd) : (roff + n);
        uint32_t pk = packh(t[2 * kk][nl], t[2 * kk + 1][nl]);
        *(uint32_t*)(dst + (size_t)row * ldo + k0 + 2 * kk) = pk;
    }
}

// ==================== LayerNorm v2: warp per token, shuffle-only ====================
__global__ void __launch_bounds__(256)
ln_h(const float* __restrict__ x, const float* __restrict__ g,
     const float* __restrict__ b, __half* __restrict__ y) {
    int t = (blockIdx.x * 256 + threadIdx.x) >> 5;   // token (warp id)
    int lane = threadIdx.x & 31;
    const float4* xr = (const float4*)(x + (size_t)t * D_);

    float4 v[8];
    float s = 0.f;
    #pragma unroll
    for (int j = 0; j < 8; ++j) {
        v[j] = xr[j * 32 + lane];
        s += v[j].x + v[j].y + v[j].z + v[j].w;
    }
    #pragma unroll
    for (int o = 16; o; o >>= 1) s += __shfl_xor_sync(~0u, s, o);
    float mean = s * (1.0f / D_);

    float s2 = 0.f;
    #pragma unroll
    for (int j = 0; j < 8; ++j) {
        float dx = v[j].x - mean, dy = v[j].y - mean;
        float dz = v[j].z - mean, dw = v[j].w - mean;
        s2 += dx * dx + dy * dy + dz * dz + dw * dw;
    }
    #pragma unroll
    for (int o = 16; o; o >>= 1) s2 += __shfl_xor_sync(~0u, s2, o);
    float rstd = rsqrtf(s2 * (1.0f / D_) + 1e-6f);

    #pragma unroll
    for (int j = 0; j < 8; ++j) {
        const float4 gv = ((const float4*)g)[j * 32 + lane];
        const float4 bv = ((const float4*)b)[j * 32 + lane];
        uint2 pk;
        pk.x = packh((v[j].x - mean) * rstd * gv.x + bv.x,
                     (v[j].y - mean) * rstd * gv.y + bv.y);
        pk.y = packh((v[j].z - mean) * rstd * gv.z + bv.z,
                     (v[j].w - mean) * rstd * gv.w + bv.w);
        *(uint2*)(y + (size_t)t * D_ + (j * 32 + lane) * 4) = pk;
    }
}

// ==================== RoPE + scatter: qkvh fp16 -> q/k/v fp16 [b,h,s,d] ====================
__global__ void rope_cvt(const __half* __restrict__ qkv, const float2* __restrict__ tab,
                         __half* __restrict__ qh, __half* __restrict__ kh,
                         __half* __restrict__ vh) {
    int t = blockIdx.x;                 // token
    int tid = threadIdx.x;              // 128
    int b = t / S_, s = t & (S_ - 1);
    int d = tid & 63;
    float2 cs = tab[s * 32 + (d & 31)];
    float c = cs.x, sn = cs.y;
    const __half* row = qkv + (size_t)t * QKV_LD;

    #pragma unroll
    for (int hh = 0; hh < 8; ++hh) {
        int h = hh * 2 + (tid >> 6);
        size_t oidx = ((size_t)(b * H_ + h) * S_ + s) * HD_ + d;
        {
            float x1 = __half2float(row[h * 64 + d]);
            float x2 = __half2float(row[h * 64 + (d ^ 32)]);
            float o = (d < 32) ? (x1 * c - x2 * sn) : (x1 * c + x2 * sn);
            qh[oidx] = __float2half(o * 0.125f);
        }
        {
            float x1 = __half2float(row[1024 + h * 64 + d]);
            float x2 = __half2float(row[1024 + h * 64 + (d ^ 32)]);
            float o = (d < 32) ? (x1 * c - x2 * sn) : (x1 * c + x2 * sn);
            kh[oidx] = __float2half(o);
        }
        vh[oidx] = row[2048 + h * 64 + d];
    }
}

// ==================== flash attention (HMMA fp16, sliding window 256) ====================
#define LK_ 72
__global__ void __launch_bounds__(256, 2)
attn_mma(const __half* __restrict__ qh, const __half* __restrict__ kh,
         const __half* __restrict__ vh, __half* __restrict__ ch) {
    extern __shared__ char smem[];
    uint32_t sQ = smem_u32(smem);
    uint32_t sK = sQ + 128 * LK_ * 2;
    uint32_t sV = sK + 128 * LK_ * 2;

    int q0 = blockIdx.x * 128;
    int h = blockIdx.y, bi = blockIdx.z;
    int tid = threadIdx.x, lane = tid & 31, w = tid >> 5;
    size_t bh = ((size_t)(bi * H_ + h)) * S_;

    for (int i = tid; i < 128 * 8; i += 256) {
        int r = i >> 3, c8 = (i & 7) * 8;
        uint4 v = *(const uint4*)(qh + (bh + q0 + r) * HD_ + c8);
        *(uint4*)(smem + (r * LK_ + c8) * 2) = v;
    }
    __syncthreads();

    uint32_t qf[4][4];
    {
        int ar = w * 16 + (lane & 15);
        int ac = (lane & 16) ? 8 : 0;
        #pragma unroll
        for (int kc = 0; kc < 4; ++kc)
            ldsm4(qf[kc], sQ + (ar * LK_ + ac + kc * 16) * 2);
    }

    float O[8][4];
    #pragma unroll
    for (int i = 0; i < 8; i++) { O[i][0]=0; O[i][1]=0; O[i][2]=0; O[i][3]=0; }
    float rm0 = -1e30f, rm1 = -1e30f, l0 = 0.f, l1 = 0.f;

    int g = lane >> 2, tq = lane & 3;
    int qrow0 = q0 + w * 16 + g;

    #pragma unroll
    for (int it = 0; it < 3; ++it) {
        int ord = 2 - it;                    // diagonal tile first
        int kbase = q0 - 256 + ord * 128;
        if (kbase + 128 <= 0) continue;

        __syncthreads();
        for (int i = tid; i < 128 * 8; i += 256) {
            int r = i >> 3, c8 = (i & 7) * 8;
            int krow = kbase + r; if (krow < 0) krow = 0;
            uint4 kv = *(const uint4*)(kh + (bh + krow) * HD_ + c8);
            uint4 vv = *(const uint4*)(vh + (bh + krow) * HD_ + c8);
            *(uint4*)(smem + (128 * LK_ + r * LK_ + c8) * 2) = kv;
            *(uint4*)(smem + (256 * LK_ + r * LK_ + c8) * 2) = vv;
        }
        __syncthreads();

        float sf[16][4];
        {
            int br = (lane & 7) + ((lane & 16) ? 8 : 0);
            int bc = (lane & 8) ? 8 : 0;
            #pragma unroll
            for (int ni2 = 0; ni2 < 8; ++ni2) {
                float s4[8] = {0,0,0,0,0,0,0,0};
                #pragma unroll
                for (int kc = 0; kc < 4; ++kc) {
                    uint32_t kf[4];
                    ldsm4(kf, sK + ((ni2 * 16 + br) * LK_ + bc + kc * 16) * 2);
                    mma16816h(s4,     qf[kc], kf + 0);
                    mma16816h(s4 + 4, qf[kc], kf + 2);
                }
                #pragma unroll
                for (int e = 0; e < 4; e++) { sf[2*ni2][e] = s4[e]; sf[2*ni2+1][e] = s4[4+e]; }
            }
        }

        float tm0 = -1e30f, tm1 = -1e30f;
        #pragma unroll
        for (int ni = 0; ni < 16; ++ni) {
            int colb = kbase + ni * 8 + tq * 2;
            #pragma unroll
            for (int e = 0; e < 2; ++e) {
                int col = colb + e;
                int r0 = qrow0 - col, r1 = qrow0 + 8 - col;
                if (!(col >= 0 && r0 >= 0 && r0 < W_)) sf[ni][e]     = -1e30f;
                if (!(col >= 0 && r1 >= 0 && r1 < W_)) sf[ni][2 + e] = -1e30f;
                tm0 = fmaxf(tm0, sf[ni][e]);
                tm1 = fmaxf(tm1, sf[ni][2 + e]);
            }
        }
        tm0 = fmaxf(tm0, __shfl_xor_sync(~0u, tm0, 1));
        tm0 = fmaxf(tm0, __shfl_xor_sync(~0u, tm0, 2));
        tm1 = fmaxf(tm1, __shfl_xor_sync(~0u, tm1, 1));
        tm1 = fmaxf(tm1, __shfl_xor_sync(~0u, tm1, 2));

        float m0 = fmaxf(rm0, tm0), m1 = fmaxf(rm1, tm1);
        float a0 = __expf(rm0 - m0), a1 = __expf(rm1 - m1);
        rm0 = m0; rm1 = m1;
        #pragma unroll
        for (int nd = 0; nd < 8; ++nd) {
            O[nd][0] *= a0; O[nd][1] *= a0; O[nd][2] *= a1; O[nd][3] *= a1;
        }
        float rs0 = 0.f, rs1 = 0.f;
        #pragma unroll
        for (int ni = 0; ni < 16; ++ni) {
            float p0 = __expf(sf[ni][0] - m0);
            float p1 = __expf(sf[ni][1] - m0);
            float p2 = __expf(sf[ni][2] - m1);
            float p3 = __expf(sf[ni][3] - m1);
            sf[ni][0] = p0; sf[ni][1] = p1; sf[ni][2] = p2; sf[ni][3] = p3;
            rs0 += p0 + p1; rs1 += p2 + p3;
        }
        rs0 += __shfl_xor_sync(~0u, rs0, 1); rs0 += __shfl_xor_sync(~0u, rs0, 2);
        rs1 += __shfl_xor_sync(~0u, rs1, 1); rs1 += __shfl_xor_sync(~0u, rs1, 2);
        l0 = l0 * a0 + rs0;
        l1 = l1 * a1 + rs1;

        #pragma unroll
        for (int j = 0; j < 8; ++j) {
            uint32_t aP[4];
            aP[0] = packh(sf[2*j][0],   sf[2*j][1]);
            aP[1] = packh(sf[2*j][2],   sf[2*j][3]);
            aP[2] = packh(sf[2*j+1][0], sf[2*j+1][1]);
            aP[3] = packh(sf[2*j+1][2], sf[2*j+1][3]);
            int sel = lane >> 3;
            int vr = 16 * j + (lane & 7) + ((sel & 1) * 8);
            #pragma unroll
            for (int np = 0; np < 4; ++np) {
                uint32_t vf[4];
                ldsm4t(vf, sV + (vr * LK_ + np * 16 + ((sel >> 1) * 8)) * 2);
                mma16816h(O[2*np],     aP, vf + 0);
                mma16816h(O[2*np + 1], aP, vf + 2);
            }
        }
    }

    float i0 = 1.0f / l0, i1 = 1.0f / l1;
    size_t r0o = ((size_t)(bi * S_ + qrow0)) * D_ + h * HD_;
    size_t r1o = ((size_t)(bi * S_ + qrow0 + 8)) * D_ + h * HD_;
    #pragma unroll
    for (int nd = 0; nd < 8; ++nd) {
        int col = nd * 8 + tq * 2;
        #pragma unroll
        for (int e = 0; e < 2; ++e) {
            ch[r0o + col + e] = __float2half(O[nd][e] * i0);
            ch[r1o + col + e] = __float2half(O[nd][2 + e] * i1);
        }
    }
}

// ==================== launch ====================
extern "C" void kernel_launch(void* const* d_in, const int* in_sizes, int n_in,
                              void* d_out, int out_size) {
    const float* hidden = (const float*)d_in[0];
    const float* wq = (const float*)d_in[1];
    const float* wk = (const float*)d_in[2];
    const float* wv = (const float*)d_in[3];
    const float* wo = (const float*)d_in[4];
    const float* w1 = (const float*)d_in[5];
    const float* w2 = (const float*)d_in[6];
    const float* w3 = (const float*)d_in[7];
    const float* ln1_g = (const float*)d_in[8];
    const float* ln1_b = (const float*)d_in[9];
    const float* ln2_g = (const float*)d_in[10];
    const float* ln2_b = (const float*)d_in[11];
    float* out = (float*)d_out;

    float *hid; float2* tab;
    __half *qkvh, *xa, *ca, *gg, *qh, *kh, *vh, *wqkv, *wot, *w13, *w2t;
    cudaGetSymbolAddress((void**)&hid, g_hid);
    cudaGetSymbolAddress((void**)&tab, g_tab);
    cudaGetSymbolAddress((void**)&qkvh, g_qkvh);
    cudaGetSymbolAddress((void**)&xa, g_xa);
    cudaGetSymbolAddress((void**)&ca, g_ca);
    cudaGetSymbolAddress((void**)&gg, g_g);
    cudaGetSymbolAddress((void**)&qh, g_qh);
    cudaGetSymbolAddress((void**)&kh, g_kh);
    cudaGetSymbolAddress((void**)&vh, g_vh);
    cudaGetSymbolAddress((void**)&wqkv, g_wqkv);
    cudaGetSymbolAddress((void**)&wot, g_wot);
    cudaGetSymbolAddress((void**)&w13, g_w13);
    cudaGetSymbolAddress((void**)&w2t, g_w2t);

    const int SMEM_G = 2 * NSTG * TILE2B;      // 110592 B (3 stages x A,B)
    cudaFuncSetAttribute(hgemm<1>, cudaFuncAttributeMaxDynamicSharedMemorySize, SMEM_G);
    cudaFuncSetAttribute(hgemm<2>, cudaFuncAttributeMaxDynamicSharedMemorySize, SMEM_G);
    cudaFuncSetAttribute(hgemm<3>, cudaFuncAttributeMaxDynamicSharedMemorySize, SMEM_G);
    const int SMEM_ATT = 3 * 128 * LK_ * 2;   // 55296 B
    cudaFuncSetAttribute(attn_mma, cudaFuncAttributeMaxDynamicSharedMemorySize, SMEM_ATT);

    // persistent side stream + events
    static cudaStream_t s2 = nullptr;
    static cudaEvent_t eFork = nullptr, eQkvW = nullptr, eTab = nullptr, eRestW = nullptr;
    if (s2 == nullptr) {
        cudaStreamCreateWithFlags(&s2, cudaStreamNonBlocking);
        cudaEventCreateWithFlags(&eFork,  cudaEventDisableTiming);
        cudaEventCreateWithFlags(&eQkvW,  cudaEventDisableTiming);
        cudaEventCreateWithFlags(&eTab,   cudaEventDisableTiming);
        cudaEventCreateWithFlags(&eRestW, cudaEventDisableTiming);
    }

    // fork: weight prep on side stream
    cudaEventRecord(eFork, 0);
    cudaStreamWaitEvent(s2, eFork, 0);
    // phase A: wq/wk/wv only (768 blocks) — minimal pre-QKV latency
    prep_all<<<768, dim3(32, 8), 0, s2>>>(wq, wk, wv, wo, w1, w2, w3,
                                          wqkv, wot, w13, w2t, 0);
    cudaEventRecord(eQkvW, s2);
    // rope table (tiny) — ready long before rope_cvt needs it
    build_tab<<<(S_ * 32) / 256, 256, 0, s2>>>(tab);
    cudaEventRecord(eTab, s2);
    // phase B: wo/w13/w2 — overlaps QKV GEMM + attention
    prep_all<<<3328, dim3(32, 8), 0, s2>>>(wq, wk, wv, wo, w1, w2, w3,
                                           wqkv, wot, w13, w2t, 768);
    cudaEventRecord(eRestW, s2);

    // --- attention sub-block (main stream) ---
    ln_h<<<TOK / 8, 256>>>(hidden, ln1_g, ln1_b, xa);
    cudaStreamWaitEvent(0, eQkvW, 0);
    hgemm<3><<<dim3(24, 32), 256, SMEM_G>>>(xa, wqkv, nullptr, nullptr, qkvh, 1024, QKV_LD);
    cudaStreamWaitEvent(0, eTab, 0);
    rope_cvt<<<TOK, 128>>>(qkvh, tab, qh, kh, vh);
    attn_mma<<<dim3(S_ / 128, H_, B_), 256, SMEM_ATT>>>(qh, kh, vh, ca);
    cudaStreamWaitEvent(0, eRestW, 0);     // wo/w13/w2 ready (hidden under QKV+attn)
    hgemm<1><<<dim3(8, 32), 256, SMEM_G>>>(ca, wot, hid, hidden, nullptr, 1024, D_);

    // --- SwiGLU MLP sub-block ---
    ln_h<<<TOK / 8, 256>>>(hid, ln2_g, ln2_b, xa);
    hgemm<2><<<dim3(64, 32), 256, SMEM_G>>>(xa, w13, nullptr, nullptr, gg, 1024, 8192);
    hgemm<1><<<dim3(8, 32), 256, SMEM_G>>>(gg, w2t, out, hid, nullptr, 4096, D_);
}